// round 2
// baseline (speedup 1.0000x reference)
#include <cuda_runtime.h>
#include <cstdint>

// ---------------- problem constants ----------------
#define BB 8
#define NL 64
#define NT 512
#define CF 128
#define HH 128
#define KK 10
#define EE 1024
#define BN_EPS 1e-4f

#define P_TOT (BB * NL * NT)          // 262144
#define PI_OFF   0
#define SIG_OFF  2621440
#define MU_OFF   5242880
#define DIST_OFF 7864320
#define ATOM_OFF 8126464
#define BOND_OFF 8140800
#define CB_OFF   8146944

// ---------------- scratch (no allocations allowed) ----------------
__device__ float g_ZL[512 * 128];      // (b*NL+l, h)  : zl*s
__device__ float g_ZT[4096 * 128];     // (b*NT+t, h)  : zt*s + (b1-mu)*s + beta
__device__ int   g_edge_is64;

// ---------------- kernel 1: fused GEMM for ZL / ZT with BN folding ----------------
// rows 0..511    -> ZL = (h_l_x @ W1[:128]) * s
// rows 512..4607 -> ZT = (h_t_x @ W1[128:]) * s + off
__global__ void gemm1_kernel(const float* __restrict__ hlx, const float* __restrict__ htx,
                             const float* __restrict__ W1,  const float* __restrict__ b1,
                             const float* __restrict__ gamma, const float* __restrict__ beta,
                             const float* __restrict__ rmean, const float* __restrict__ rvar)
{
    __shared__ float sX[32][33];
    __shared__ float sWt[32][128];

    const int row0 = blockIdx.x * 32;
    const bool isL = (row0 < 512);
    const float* X   = isL ? hlx : htx;
    const int    xr0 = isL ? row0 : row0 - 512;
    const float* Wh  = W1 + (isL ? 0 : 128 * 128);

    const int tid = threadIdx.x;
    const int tx = tid & 15, ty = tid >> 4;

    float acc[2][8];
#pragma unroll
    for (int i = 0; i < 2; i++)
#pragma unroll
        for (int j = 0; j < 8; j++) acc[i][j] = 0.f;

    for (int k0 = 0; k0 < 128; k0 += 32) {
        __syncthreads();
        {   // stage X tile 32x32 (float4 loads)
            int idx = tid * 4;
            int r = idx >> 5, c = idx & 31;
            float4 v = *reinterpret_cast<const float4*>(X + (xr0 + r) * 128 + k0 + c);
            sX[r][c] = v.x; sX[r][c + 1] = v.y; sX[r][c + 2] = v.z; sX[r][c + 3] = v.w;
        }
#pragma unroll
        for (int j = 0; j < 16; j++) {  // stage W tile 32x128
            int idx = tid + 256 * j;
            int r = idx >> 7, c = idx & 127;
            sWt[r][c] = Wh[(k0 + r) * 128 + c];
        }
        __syncthreads();
#pragma unroll
        for (int ck = 0; ck < 32; ++ck) {
            float x0 = sX[ty * 2][ck];
            float x1 = sX[ty * 2 + 1][ck];
#pragma unroll
            for (int j = 0; j < 8; j++) {
                float w = sWt[ck][tx + 16 * j];
                acc[0][j] += x0 * w;
                acc[1][j] += x1 * w;
            }
        }
    }

#pragma unroll
    for (int j = 0; j < 8; j++) {
        int h = tx + 16 * j;
        float s   = gamma[h] * rsqrtf(rvar[h] + BN_EPS);
        float off = (b1[h] - rmean[h]) * s + beta[h];
#pragma unroll
        for (int i = 0; i < 2; i++) {
            int r = row0 + ty * 2 + i;
            float v = acc[i][j] * s;
            if (isL) g_ZL[r * 128 + h] = v;
            else     g_ZT[(r - 512) * 128 + h] = v + off;
        }
    }
}

// ---------------- edge dtype detection ----------------
__global__ void detect_kernel(const void* __restrict__ edge)
{
    __shared__ int any32;
    int tid = threadIdx.x;
    if (tid == 0) any32 = 0;
    __syncthreads();
    const int* p = reinterpret_cast<const int*>(edge);
    if (p[2 * tid + 1] != 0) atomicOr(&any32, 1);
    __syncthreads();
    if (tid == 0) g_edge_is64 = (any32 == 0) ? 1 : 0;
}

// ---------------- atom types: [512,128] @ [128,28] ----------------
__global__ void atom_kernel(const float* __restrict__ hlx, const float* __restrict__ Wat,
                            const float* __restrict__ bat, float* __restrict__ out)
{
    const int row = blockIdx.x;
    const int k = threadIdx.x;
    if (k >= 28) return;
    float acc = bat[k];
    const float* x = hlx + row * 128;
#pragma unroll 4
    for (int c = 0; c < 128; c++) acc += x[c] * Wat[c * 28 + k];
    out[ATOM_OFF + row * 28 + k] = acc;
}

// ---------------- bond types: gather + [1024,256] @ [256,6] ----------------
__global__ void bond_kernel(const float* __restrict__ hlx, const void* __restrict__ edge,
                            const float* __restrict__ Wbd, const float* __restrict__ bbd,
                            float* __restrict__ out)
{
    const int gid = blockIdx.x * blockDim.x + threadIdx.x;
    if (gid >= EE * 6) return;
    const int e = gid / 6, k = gid % 6;
    int src, dst;
    if (g_edge_is64) {
        const long long* p = reinterpret_cast<const long long*>(edge);
        src = (int)p[e]; dst = (int)p[EE + e];
    } else {
        const int* p = reinterpret_cast<const int*>(edge);
        src = p[e]; dst = p[EE + e];
    }
    float acc = bbd[k];
    const float* xs = hlx + src * 128;
    const float* xd = hlx + dst * 128;
#pragma unroll 4
    for (int c = 0; c < 128; c++) {
        acc += xs[c] * Wbd[c * 6 + k];
        acc += xd[c] * Wbd[(128 + c) * 6 + k];
    }
    out[BOND_OFF + e * 6 + k] = acc;
}

// ---------------- main pair kernel ----------------
// block = (b,l) (512 blocks x 128 threads); each thread owns 4 t values.
// inner product over h with packed fp32x2 FMA (k-pairs packed, c broadcast).
__global__ void __launch_bounds__(128, 2)
pair_kernel(const float* __restrict__ hlpos, const float* __restrict__ htpos,
            const float* __restrict__ Wpi,  const float* __restrict__ bpi,
            const float* __restrict__ Wsig, const float* __restrict__ bsig,
            const float* __restrict__ Wmu,  const float* __restrict__ bmu,
            float* __restrict__ out)
{
    __shared__ float sW[128 * 32];     // [h][j], j: 0-9 Wpi, 10-19 Wsig, 20-29 Wmu, 30/31 pad
    __shared__ float sBias[32];
    __shared__ float sZL[128];
    __shared__ float sZT[512 * 9];     // h-chunk of 8, stride 9 (odd -> bank-conflict-free)

    const int tid = threadIdx.x;
    const int bid = blockIdx.x;        // = b*64 + l
    const int b = bid >> 6;

#pragma unroll
    for (int j = 0; j < 32; j++) {
        float w;
        if (j < 10)      w = Wpi [tid * 10 + j];
        else if (j < 20) w = Wsig[tid * 10 + (j - 10)];
        else if (j < 30) w = Wmu [tid * 10 + (j - 20)];
        else             w = 0.f;
        sW[tid * 32 + j] = w;
    }
    if (tid < 32) {
        float bv;
        if (tid < 10)      bv = bpi [tid];
        else if (tid < 20) bv = bsig[tid - 10];
        else if (tid < 30) bv = bmu [tid - 20];
        else               bv = 0.f;
        sBias[tid] = bv;
    }
    sZL[tid] = g_ZL[bid * 128 + tid];

    unsigned long long acc[4][15];
#pragma unroll
    for (int tt = 0; tt < 4; tt++)
#pragma unroll
        for (int k2 = 0; k2 < 15; k2++) acc[tt][k2] = 0ull;

    const float* ztb = g_ZT + b * 512 * 128;

    for (int h0 = 0; h0 < 128; h0 += 8) {
        __syncthreads();
        // stage ZT[b][0..511][h0..h0+7] -> shared, coalesced float4 reads
#pragma unroll
        for (int it = 0; it < 8; ++it) {
            int lin = it * 512 + tid * 4;
            int t = lin >> 3, hh = lin & 7;
            float4 v = *reinterpret_cast<const float4*>(ztb + t * 128 + h0 + hh);
            float* d = &sZT[t * 9 + hh];
            d[0] = v.x; d[1] = v.y; d[2] = v.z; d[3] = v.w;
        }
        __syncthreads();
#pragma unroll
        for (int hh = 0; hh < 8; ++hh) {
            const int h = h0 + hh;
            const float zl = sZL[h];
            unsigned long long w2[15];
#pragma unroll
            for (int k2 = 0; k2 < 15; k2++)
                w2[k2] = *reinterpret_cast<const unsigned long long*>(&sW[h * 32 + 2 * k2]);
#pragma unroll
            for (int tt = 0; tt < 4; tt++) {
                float zt = sZT[(tid + 128 * tt) * 9 + hh];
                float z = zl + zt;
                float c = (z > 0.f) ? z : (__expf(z) - 1.f);
                unsigned long long c2;
                asm("mov.b64 %0, {%1, %1};" : "=l"(c2) : "r"(__float_as_uint(c)));
#pragma unroll
                for (int k2 = 0; k2 < 15; k2++)
                    asm("fma.rn.f32x2 %0, %1, %2, %0;"
                        : "+l"(acc[tt][k2]) : "l"(c2), "l"(w2[k2]));
            }
        }
    }

    // -------- epilogue --------
    const float plx = hlpos[bid * 3 + 0];
    const float ply = hlpos[bid * 3 + 1];
    const float plz = hlpos[bid * 3 + 2];
    const float pl2 = plx * plx + ply * ply + plz * plz;

#pragma unroll
    for (int tt = 0; tt < 4; tt++) {
        const int t = tid + 128 * tt;
        const int p = bid * 512 + t;

        float v[30];
#pragma unroll
        for (int k2 = 0; k2 < 15; k2++) {
            unsigned int ulo, uhi;
            asm("mov.b64 {%0, %1}, %2;" : "=r"(ulo), "=r"(uhi) : "l"(acc[tt][k2]));
            v[2 * k2]     = __uint_as_float(ulo) + sBias[2 * k2];
            v[2 * k2 + 1] = __uint_as_float(uhi) + sBias[2 * k2 + 1];
        }

        // softmax over v[0..9]
        float m = v[0];
#pragma unroll
        for (int k = 1; k < 10; k++) m = fmaxf(m, v[k]);
        float e[10], s = 0.f;
#pragma unroll
        for (int k = 0; k < 10; k++) { e[k] = __expf(v[k] - m); s += e[k]; }
        float inv = __fdividef(1.f, s);
#pragma unroll
        for (int k = 0; k < 10; k++) out[PI_OFF + p * 10 + k] = e[k] * inv;

        // sigma = elu(x) + 1.1
#pragma unroll
        for (int k = 0; k < 10; k++) {
            float x = v[10 + k];
            float r = (x > 0.f) ? x : (__expf(x) - 1.f);
            out[SIG_OFF + p * 10 + k] = r + 1.1f;
        }
        // mu = elu(x) + 1.0
#pragma unroll
        for (int k = 0; k < 10; k++) {
            float x = v[20 + k];
            float r = (x > 0.f) ? x : (__expf(x) - 1.f);
            out[MU_OFF + p * 10 + k] = r + 1.0f;
        }

        const float* pt = htpos + (b * 512 + t) * 3;
        float ptx = pt[0], pty = pt[1], ptz = pt[2];
        float d2 = -2.f * (plx * ptx + ply * pty + plz * ptz)
                 + (ptx * ptx + pty * pty + ptz * ptz) + pl2;
        out[DIST_OFF + p] = sqrtf(d2);
        out[CB_OFF + p] = (float)b;
    }
}

// ---------------- launch ----------------
extern "C" void kernel_launch(void* const* d_in, const int* in_sizes, int n_in,
                              void* d_out, int out_size)
{
    const float* hlx   = (const float*)d_in[0];
    const float* htx   = (const float*)d_in[1];
    const float* hlpos = (const float*)d_in[2];
    const float* htpos = (const float*)d_in[3];
    const void*  edge  = d_in[4];
    const float* W1    = (const float*)d_in[5];
    const float* b1    = (const float*)d_in[6];
    const float* gamma = (const float*)d_in[7];
    const float* beta  = (const float*)d_in[8];
    const float* rmean = (const float*)d_in[9];
    const float* rvar  = (const float*)d_in[10];
    const float* Wpi   = (const float*)d_in[11];
    const float* bpi   = (const float*)d_in[12];
    const float* Wsig  = (const float*)d_in[13];
    const float* bsig  = (const float*)d_in[14];
    const float* Wmu   = (const float*)d_in[15];
    const float* bmu   = (const float*)d_in[16];
    const float* Wat   = (const float*)d_in[17];
    const float* bat   = (const float*)d_in[18];
    const float* Wbd   = (const float*)d_in[19];
    const float* bbd   = (const float*)d_in[20];
    float* out = (float*)d_out;

    detect_kernel<<<1, 1024>>>(edge);
    gemm1_kernel<<<144, 256>>>(hlx, htx, W1, b1, gamma, beta, rmean, rvar);
    atom_kernel<<<512, 32>>>(hlx, Wat, bat, out);
    bond_kernel<<<24, 256>>>(hlx, edge, Wbd, bbd, out);
    pair_kernel<<<512, 128>>>(hlpos, htpos, Wpi, bpi, Wsig, bsig, Wmu, bmu, out);
}

// round 3
// speedup vs baseline: 1.1459x; 1.1459x over previous
#include <cuda_runtime.h>
#include <cstdint>

// ---------------- problem constants ----------------
#define BB 8
#define NL 64
#define NT 512
#define CF 128
#define HH 128
#define KK 10
#define EE 1024
#define BN_EPS 1e-4f

#define PI_OFF   0
#define SIG_OFF  2621440
#define MU_OFF   5242880
#define DIST_OFF 7864320
#define ATOM_OFF 8126464
#define BOND_OFF 8140800
#define CB_OFF   8146944

// ---------------- scratch ----------------
__device__ float g_ZL[512 * 128];      // (b*NL+l, h)  : zl*s
__device__ float g_ZT[4096 * 128];     // (b*NT+t, h)  : zt*s + (b1-mu)*s + beta

// ================= prep kernel: gemm1 (blocks 0..143), bond (144..271), atom (272..335) =================
__global__ void __launch_bounds__(256)
prep_kernel(const float* __restrict__ hlx, const float* __restrict__ htx,
            const void*  __restrict__ edge,
            const float* __restrict__ W1,  const float* __restrict__ b1,
            const float* __restrict__ gamma, const float* __restrict__ beta,
            const float* __restrict__ rmean, const float* __restrict__ rvar,
            const float* __restrict__ Wat, const float* __restrict__ bat,
            const float* __restrict__ Wbd, const float* __restrict__ bbd,
            float* __restrict__ out)
{
    __shared__ __align__(16) char s_buf[20800];
    const int tid = threadIdx.x;

    if (blockIdx.x < 144) {
        // ---------- GEMM1: ZL/ZT with BN folding ----------
        float (*sX)[33]   = reinterpret_cast<float(*)[33]>(s_buf);                 // 32x33
        float (*sWt)[128] = reinterpret_cast<float(*)[128]>(s_buf + 32*33*4);      // 32x128

        const int row0 = blockIdx.x * 32;
        const bool isL = (row0 < 512);
        const float* X   = isL ? hlx : htx;
        const int    xr0 = isL ? row0 : row0 - 512;
        const float* Wh  = W1 + (isL ? 0 : 128 * 128);

        const int tx = tid & 15, ty = tid >> 4;

        float acc[2][8];
#pragma unroll
        for (int i = 0; i < 2; i++)
#pragma unroll
            for (int j = 0; j < 8; j++) acc[i][j] = 0.f;

        for (int k0 = 0; k0 < 128; k0 += 32) {
            __syncthreads();
            {
                int idx = tid * 4;
                int r = idx >> 5, c = idx & 31;
                float4 v = *reinterpret_cast<const float4*>(X + (xr0 + r) * 128 + k0 + c);
                sX[r][c] = v.x; sX[r][c + 1] = v.y; sX[r][c + 2] = v.z; sX[r][c + 3] = v.w;
            }
#pragma unroll
            for (int j = 0; j < 16; j++) {
                int idx = tid + 256 * j;
                int r = idx >> 7, c = idx & 127;
                sWt[r][c] = Wh[(k0 + r) * 128 + c];
            }
            __syncthreads();
#pragma unroll
            for (int ck = 0; ck < 32; ++ck) {
                float x0 = sX[ty * 2][ck];
                float x1 = sX[ty * 2 + 1][ck];
#pragma unroll
                for (int j = 0; j < 8; j++) {
                    float w = sWt[ck][tx + 16 * j];
                    acc[0][j] += x0 * w;
                    acc[1][j] += x1 * w;
                }
            }
        }
#pragma unroll
        for (int j = 0; j < 8; j++) {
            int h = tx + 16 * j;
            float s   = gamma[h] * rsqrtf(rvar[h] + BN_EPS);
            float off = (b1[h] - rmean[h]) * s + beta[h];
#pragma unroll
            for (int i = 0; i < 2; i++) {
                int r = row0 + ty * 2 + i;
                float v = acc[i][j] * s;
                if (isL) g_ZL[r * 128 + h] = v;
                else     g_ZT[(r - 512) * 128 + h] = v + off;
            }
        }
    } else if (blockIdx.x < 272) {
        // ---------- BOND: warp per edge, block-local dtype detection ----------
        int* s_is64 = reinterpret_cast<int*>(s_buf);
        if (tid == 0) *s_is64 = 1;
        __syncthreads();
        const int* p32 = reinterpret_cast<const int*>(edge);
        // sample first 256 odd 32-bit words: all zero  => int64 layout
        if (p32[2 * tid + 1] != 0) *s_is64 = 0;
        __syncthreads();
        const int is64 = *s_is64;

        const int wid = tid >> 5, lane = tid & 31;
        const int e = (blockIdx.x - 144) * 8 + wid;
        int src, dst;
        if (is64) {
            const long long* p = reinterpret_cast<const long long*>(edge);
            src = (int)p[e]; dst = (int)p[EE + e];
        } else {
            src = p32[e]; dst = p32[EE + e];
        }
        float4 xs = *reinterpret_cast<const float4*>(hlx + src * 128 + lane * 4);
        float4 xd = *reinterpret_cast<const float4*>(hlx + dst * 128 + lane * 4);
        float acc[6];
#pragma unroll
        for (int j = 0; j < 6; j++) acc[j] = 0.f;
        const float* xsv = reinterpret_cast<const float*>(&xs);
        const float* xdv = reinterpret_cast<const float*>(&xd);
#pragma unroll
        for (int i = 0; i < 4; i++) {
            int c = lane * 4 + i;
#pragma unroll
            for (int j = 0; j < 6; j++) {
                acc[j] += xsv[i] * __ldg(Wbd + c * 6 + j);
                acc[j] += xdv[i] * __ldg(Wbd + (128 + c) * 6 + j);
            }
        }
#pragma unroll
        for (int off = 16; off > 0; off >>= 1)
#pragma unroll
            for (int j = 0; j < 6; j++)
                acc[j] += __shfl_down_sync(0xffffffffu, acc[j], off);
        if (lane == 0) {
#pragma unroll
            for (int j = 0; j < 6; j++)
                out[BOND_OFF + e * 6 + j] = acc[j] + bbd[j];
        }
    } else {
        // ---------- ATOM: 8 rows per block, shared transposed Wat ----------
        float* sWat = reinterpret_cast<float*>(s_buf);          // [28][129]
        float* sX   = sWat + 28 * 129;                          // [8][128]
        const int aid = blockIdx.x - 272;                       // 0..63
        const int row0 = aid * 8;

        for (int idx = tid; idx < 128 * 28; idx += 256) {
            int c = idx / 28;
            int k = idx - c * 28;
            sWat[k * 129 + c] = Wat[idx];
        }
        for (int idx = tid; idx < 8 * 128; idx += 256) {
            sX[idx] = hlx[row0 * 128 + idx];
        }
        __syncthreads();

        const int r = tid >> 5, k = tid & 31;
        if (k < 28) {
            float acc = bat[k];
            const float* xr = sX + r * 128;
            const float* wr = sWat + k * 129;
#pragma unroll 8
            for (int c = 0; c < 128; c++) acc += xr[c] * wr[c];
            out[ATOM_OFF + (row0 + r) * 28 + k] = acc;
        }
    }
}

// ================= pair kernel =================
// block = (b,l) (512 blocks x 128 threads); thread owns t = tid + 128*tt, tt=0..3.
// double-buffered ZT chunk staging (reg prefetch), packed f32x2 FMA over k.
__global__ void __launch_bounds__(128, 2)
pair_kernel(const float* __restrict__ hlpos, const float* __restrict__ htpos,
            const float* __restrict__ Wpi,  const float* __restrict__ bpi,
            const float* __restrict__ Wsig, const float* __restrict__ bsig,
            const float* __restrict__ Wmu,  const float* __restrict__ bmu,
            float* __restrict__ out)
{
    __shared__ float sW[128 * 32];     // [h][j], j: 0-9 Wpi, 10-19 Wsig, 20-29 Wmu
    __shared__ float sBias[32];
    __shared__ float sZL[128];
    __shared__ float sZT[2][512 * 9 + 8];   // [buf][t*9 + hh], stride 9 conflict-free

    const int tid = threadIdx.x;
    const int bid = blockIdx.x;        // = b*64 + l
    const int b = bid >> 6;

#pragma unroll
    for (int j = 0; j < 32; j++) {
        float w;
        if (j < 10)      w = Wpi [tid * 10 + j];
        else if (j < 20) w = Wsig[tid * 10 + (j - 10)];
        else if (j < 30) w = Wmu [tid * 10 + (j - 20)];
        else             w = 0.f;
        sW[tid * 32 + j] = w;
    }
    if (tid < 32) {
        float bv;
        if (tid < 10)      bv = bpi [tid];
        else if (tid < 20) bv = bsig[tid - 10];
        else if (tid < 30) bv = bmu [tid - 20];
        else               bv = 0.f;
        sBias[tid] = bv;
    }
    sZL[tid] = g_ZL[bid * 128 + tid];

    unsigned long long acc[4][15];
#pragma unroll
    for (int tt = 0; tt < 4; tt++)
#pragma unroll
        for (int k2 = 0; k2 < 15; k2++) acc[tt][k2] = 0ull;

    const float* ztb = g_ZT + b * 512 * 128;

    // sector-exact prefetch: lane pair (2k,2k+1) covers the full 32B h-chunk of row t=k
    float4 pf[8];
#pragma unroll
    for (int i = 0; i < 8; i++) {
        int lin = i * 128 + tid;
        int t = lin >> 1, part = (lin & 1) * 4;
        pf[i] = *reinterpret_cast<const float4*>(ztb + t * 128 + 0 + part);
    }
    __syncthreads();   // sW / sZL ready

    int buf = 0;
    for (int c = 0; c < 16; c++) {
        // store prefetched chunk into shared
#pragma unroll
        for (int i = 0; i < 8; i++) {
            int lin = i * 128 + tid;
            int t = lin >> 1, part = (lin & 1) * 4;
            float* d = &sZT[buf][t * 9 + part];
            d[0] = pf[i].x; d[1] = pf[i].y; d[2] = pf[i].z; d[3] = pf[i].w;
        }
        __syncthreads();
        // issue next chunk's loads (latency hidden under compute)
        if (c < 15) {
            const int h0n = (c + 1) * 8;
#pragma unroll
            for (int i = 0; i < 8; i++) {
                int lin = i * 128 + tid;
                int t = lin >> 1, part = (lin & 1) * 4;
                pf[i] = *reinterpret_cast<const float4*>(ztb + t * 128 + h0n + part);
            }
        }
        // compute on current chunk
        const int h0 = c * 8;
#pragma unroll
        for (int hh = 0; hh < 8; ++hh) {
            const int h = h0 + hh;
            const float zl = sZL[h];
            unsigned long long w2[15];
#pragma unroll
            for (int k2 = 0; k2 < 15; k2++)
                w2[k2] = *reinterpret_cast<const unsigned long long*>(&sW[h * 32 + 2 * k2]);
#pragma unroll
            for (int tt = 0; tt < 4; tt++) {
                float zt = sZT[buf][(tid + 128 * tt) * 9 + hh];
                float z = zl + zt;
                float cc = (z > 0.f) ? z : (__expf(z) - 1.f);
                unsigned long long c2;
                asm("mov.b64 %0, {%1, %1};" : "=l"(c2) : "r"(__float_as_uint(cc)));
#pragma unroll
                for (int k2 = 0; k2 < 15; k2++)
                    asm("fma.rn.f32x2 %0, %1, %2, %0;"
                        : "+l"(acc[tt][k2]) : "l"(c2), "l"(w2[k2]));
            }
        }
        buf ^= 1;
    }

    // -------- epilogue --------
    const float plx = hlpos[bid * 3 + 0];
    const float ply = hlpos[bid * 3 + 1];
    const float plz = hlpos[bid * 3 + 2];
    const float pl2 = plx * plx + ply * ply + plz * plz;

#pragma unroll
    for (int tt = 0; tt < 4; tt++) {
        const int t = tid + 128 * tt;
        const int p = bid * 512 + t;

        float v[30];
#pragma unroll
        for (int k2 = 0; k2 < 15; k2++) {
            unsigned int ulo, uhi;
            asm("mov.b64 {%0, %1}, %2;" : "=r"(ulo), "=r"(uhi) : "l"(acc[tt][k2]));
            v[2 * k2]     = __uint_as_float(ulo) + sBias[2 * k2];
            v[2 * k2 + 1] = __uint_as_float(uhi) + sBias[2 * k2 + 1];
        }

        float m = v[0];
#pragma unroll
        for (int k = 1; k < 10; k++) m = fmaxf(m, v[k]);
        float e[10], s = 0.f;
#pragma unroll
        for (int k = 0; k < 10; k++) { e[k] = __expf(v[k] - m); s += e[k]; }
        float inv = __fdividef(1.f, s);
#pragma unroll
        for (int k = 0; k < 10; k++) out[PI_OFF + p * 10 + k] = e[k] * inv;

#pragma unroll
        for (int k = 0; k < 10; k++) {
            float x = v[10 + k];
            float r = (x > 0.f) ? x : (__expf(x) - 1.f);
            out[SIG_OFF + p * 10 + k] = r + 1.1f;
        }
#pragma unroll
        for (int k = 0; k < 10; k++) {
            float x = v[20 + k];
            float r = (x > 0.f) ? x : (__expf(x) - 1.f);
            out[MU_OFF + p * 10 + k] = r + 1.0f;
        }

        const float* pt = htpos + (b * 512 + t) * 3;
        float ptx = pt[0], pty = pt[1], ptz = pt[2];
        float d2 = -2.f * (plx * ptx + ply * pty + plz * ptz)
                 + (ptx * ptx + pty * pty + ptz * ptz) + pl2;
        out[DIST_OFF + p] = sqrtf(d2);
        out[CB_OFF + p] = (float)b;
    }
}

// ---------------- launch ----------------
extern "C" void kernel_launch(void* const* d_in, const int* in_sizes, int n_in,
                              void* d_out, int out_size)
{
    const float* hlx   = (const float*)d_in[0];
    const float* htx   = (const float*)d_in[1];
    const float* hlpos = (const float*)d_in[2];
    const float* htpos = (const float*)d_in[3];
    const void*  edge  = d_in[4];
    const float* W1    = (const float*)d_in[5];
    const float* b1    = (const float*)d_in[6];
    const float* gamma = (const float*)d_in[7];
    const float* beta  = (const float*)d_in[8];
    const float* rmean = (const float*)d_in[9];
    const float* rvar  = (const float*)d_in[10];
    const float* Wpi   = (const float*)d_in[11];
    const float* bpi   = (const float*)d_in[12];
    const float* Wsig  = (const float*)d_in[13];
    const float* bsig  = (const float*)d_in[14];
    const float* Wmu   = (const float*)d_in[15];
    const float* bmu   = (const float*)d_in[16];
    const float* Wat   = (const float*)d_in[17];
    const float* bat   = (const float*)d_in[18];
    const float* Wbd   = (const float*)d_in[19];
    const float* bbd   = (const float*)d_in[20];
    float* out = (float*)d_out;

    prep_kernel<<<336, 256>>>(hlx, htx, edge, W1, b1, gamma, beta, rmean, rvar,
                              Wat, bat, Wbd, bbd, out);
    pair_kernel<<<512, 128>>>(hlpos, htpos, Wpi, bpi, Wsig, bsig, Wmu, bmu, out);
}

// round 4
// speedup vs baseline: 1.2811x; 1.1180x over previous
#include <cuda_runtime.h>
#include <cstdint>

// ---------------- problem constants ----------------
#define BB 8
#define NL 64
#define NT 512
#define CF 128
#define HH 128
#define KK 10
#define EE 1024
#define BN_EPS 1e-4f

#define PI_OFF   0
#define SIG_OFF  2621440
#define MU_OFF   5242880
#define DIST_OFF 7864320
#define ATOM_OFF 8126464
#define BOND_OFF 8140800
#define CB_OFF   8146944

// ---------------- scratch ----------------
__device__ float g_ZL[512 * 128];      // (b*NL+l, h)  : zl*s
__device__ float g_ZT[4096 * 128];     // (b*NT+t, h)  : zt*s + (b1-mu)*s + beta

// ================= prep kernel: gemm1 (blocks 0..143), bond (144..271), atom (272..335) =================
__global__ void __launch_bounds__(256)
prep_kernel(const float* __restrict__ hlx, const float* __restrict__ htx,
            const void*  __restrict__ edge,
            const float* __restrict__ W1,  const float* __restrict__ b1,
            const float* __restrict__ gamma, const float* __restrict__ beta,
            const float* __restrict__ rmean, const float* __restrict__ rvar,
            const float* __restrict__ Wat, const float* __restrict__ bat,
            const float* __restrict__ Wbd, const float* __restrict__ bbd,
            float* __restrict__ out)
{
    __shared__ __align__(16) char s_buf[20800];
    const int tid = threadIdx.x;

    if (blockIdx.x < 144) {
        // ---------- GEMM1: ZL/ZT with BN folding ----------
        float (*sX)[33]   = reinterpret_cast<float(*)[33]>(s_buf);                 // 32x33
        float (*sWt)[128] = reinterpret_cast<float(*)[128]>(s_buf + 32*33*4);      // 32x128

        const int row0 = blockIdx.x * 32;
        const bool isL = (row0 < 512);
        const float* X   = isL ? hlx : htx;
        const int    xr0 = isL ? row0 : row0 - 512;
        const float* Wh  = W1 + (isL ? 0 : 128 * 128);

        const int tx = tid & 15, ty = tid >> 4;

        float acc[2][8];
#pragma unroll
        for (int i = 0; i < 2; i++)
#pragma unroll
            for (int j = 0; j < 8; j++) acc[i][j] = 0.f;

        for (int k0 = 0; k0 < 128; k0 += 32) {
            __syncthreads();
            {
                int idx = tid * 4;
                int r = idx >> 5, c = idx & 31;
                float4 v = *reinterpret_cast<const float4*>(X + (xr0 + r) * 128 + k0 + c);
                sX[r][c] = v.x; sX[r][c + 1] = v.y; sX[r][c + 2] = v.z; sX[r][c + 3] = v.w;
            }
#pragma unroll
            for (int j = 0; j < 16; j++) {
                int idx = tid + 256 * j;
                int r = idx >> 7, c = idx & 127;
                sWt[r][c] = Wh[(k0 + r) * 128 + c];
            }
            __syncthreads();
#pragma unroll
            for (int ck = 0; ck < 32; ++ck) {
                float x0 = sX[ty * 2][ck];
                float x1 = sX[ty * 2 + 1][ck];
#pragma unroll
                for (int j = 0; j < 8; j++) {
                    float w = sWt[ck][tx + 16 * j];
                    acc[0][j] += x0 * w;
                    acc[1][j] += x1 * w;
                }
            }
        }
#pragma unroll
        for (int j = 0; j < 8; j++) {
            int h = tx + 16 * j;
            float s   = gamma[h] * rsqrtf(rvar[h] + BN_EPS);
            float off = (b1[h] - rmean[h]) * s + beta[h];
#pragma unroll
            for (int i = 0; i < 2; i++) {
                int r = row0 + ty * 2 + i;
                float v = acc[i][j] * s;
                if (isL) g_ZL[r * 128 + h] = v;
                else     g_ZT[(r - 512) * 128 + h] = v + off;
            }
        }
    } else if (blockIdx.x < 272) {
        // ---------- BOND: warp per edge, block-local dtype detection ----------
        int* s_is64 = reinterpret_cast<int*>(s_buf);
        if (tid == 0) *s_is64 = 1;
        __syncthreads();
        const int* p32 = reinterpret_cast<const int*>(edge);
        if (p32[2 * tid + 1] != 0) *s_is64 = 0;
        __syncthreads();
        const int is64 = *s_is64;

        const int wid = tid >> 5, lane = tid & 31;
        const int e = (blockIdx.x - 144) * 8 + wid;
        int src, dst;
        if (is64) {
            const long long* p = reinterpret_cast<const long long*>(edge);
            src = (int)p[e]; dst = (int)p[EE + e];
        } else {
            src = p32[e]; dst = p32[EE + e];
        }
        float4 xs = *reinterpret_cast<const float4*>(hlx + src * 128 + lane * 4);
        float4 xd = *reinterpret_cast<const float4*>(hlx + dst * 128 + lane * 4);
        float acc[6];
#pragma unroll
        for (int j = 0; j < 6; j++) acc[j] = 0.f;
        const float* xsv = reinterpret_cast<const float*>(&xs);
        const float* xdv = reinterpret_cast<const float*>(&xd);
#pragma unroll
        for (int i = 0; i < 4; i++) {
            int c = lane * 4 + i;
#pragma unroll
            for (int j = 0; j < 6; j++) {
                acc[j] += xsv[i] * __ldg(Wbd + c * 6 + j);
                acc[j] += xdv[i] * __ldg(Wbd + (128 + c) * 6 + j);
            }
        }
#pragma unroll
        for (int off = 16; off > 0; off >>= 1)
#pragma unroll
            for (int j = 0; j < 6; j++)
                acc[j] += __shfl_down_sync(0xffffffffu, acc[j], off);
        if (lane == 0) {
#pragma unroll
            for (int j = 0; j < 6; j++)
                out[BOND_OFF + e * 6 + j] = acc[j] + bbd[j];
        }
    } else {
        // ---------- ATOM: 8 rows per block, shared transposed Wat ----------
        float* sWat = reinterpret_cast<float*>(s_buf);          // [28][129]
        float* sX   = sWat + 28 * 129;                          // [8][128]
        const int aid = blockIdx.x - 272;                       // 0..63
        const int row0 = aid * 8;

        for (int idx = tid; idx < 128 * 28; idx += 256) {
            int c = idx / 28;
            int k = idx - c * 28;
            sWat[k * 129 + c] = Wat[idx];
        }
        for (int idx = tid; idx < 8 * 128; idx += 256) {
            sX[idx] = hlx[row0 * 128 + idx];
        }
        __syncthreads();

        const int r = tid >> 5, k = tid & 31;
        if (k < 28) {
            float acc = bat[k];
            const float* xr = sX + r * 128;
            const float* wr = sWat + k * 129;
#pragma unroll 8
            for (int c = 0; c < 128; c++) acc += xr[c] * wr[c];
            out[ATOM_OFF + (row0 + r) * 28 + k] = acc;
        }
    }
}

// ================= pair kernel =================
// grid = 1024: block = (b*64+l, half). 128 threads, each owns tt=2 t-values
// (t = half*256 + tid + 128*tt). Double-buffered ZT staging via reg prefetch.
// 60-reg u64 accumulators, packed f32x2 FMA over k. 4 blocks/SM.
__global__ void __launch_bounds__(128, 4)
pair_kernel(const float* __restrict__ hlpos, const float* __restrict__ htpos,
            const float* __restrict__ Wpi,  const float* __restrict__ bpi,
            const float* __restrict__ Wsig, const float* __restrict__ bsig,
            const float* __restrict__ Wmu,  const float* __restrict__ bmu,
            float* __restrict__ out)
{
    __shared__ float sW[128 * 32];          // [h][j], j: 0-9 Wpi, 10-19 Wsig, 20-29 Wmu
    __shared__ float sBias[32];
    __shared__ float sZL[128];
    __shared__ float sZT[2][256 * 9 + 8];   // [buf][t*9 + hh], stride 9 conflict-free

    const int tid = threadIdx.x;
    const int bid2 = blockIdx.x >> 1;       // = b*64 + l
    const int half = blockIdx.x & 1;
    const int b = bid2 >> 6;
    const int t0 = half * 256;

#pragma unroll
    for (int j = 0; j < 32; j++) {
        float w;
        if (j < 10)      w = Wpi [tid * 10 + j];
        else if (j < 20) w = Wsig[tid * 10 + (j - 10)];
        else if (j < 30) w = Wmu [tid * 10 + (j - 20)];
        else             w = 0.f;
        sW[tid * 32 + j] = w;
    }
    if (tid < 32) {
        float bv;
        if (tid < 10)      bv = bpi [tid];
        else if (tid < 20) bv = bsig[tid - 10];
        else if (tid < 30) bv = bmu [tid - 20];
        else               bv = 0.f;
        sBias[tid] = bv;
    }
    sZL[tid] = g_ZL[bid2 * 128 + tid];

    unsigned long long acc[2][15];
#pragma unroll
    for (int tt = 0; tt < 2; tt++)
#pragma unroll
        for (int k2 = 0; k2 < 15; k2++) acc[tt][k2] = 0ull;

    const float* ztb = g_ZT + (b * 512 + t0) * 128;

    // sector-exact prefetch: lane pair (2k,2k+1) covers the full 32B h-chunk of row t=k
    float4 pf[4];
#pragma unroll
    for (int i = 0; i < 4; i++) {
        int lin = i * 128 + tid;
        int t = lin >> 1, part = (lin & 1) * 4;
        pf[i] = *reinterpret_cast<const float4*>(ztb + t * 128 + 0 + part);
    }
    __syncthreads();   // sW / sZL ready

    int buf = 0;
    for (int c = 0; c < 16; c++) {
        // store prefetched chunk into shared
#pragma unroll
        for (int i = 0; i < 4; i++) {
            int lin = i * 128 + tid;
            int t = lin >> 1, part = (lin & 1) * 4;
            float* d = &sZT[buf][t * 9 + part];
            d[0] = pf[i].x; d[1] = pf[i].y; d[2] = pf[i].z; d[3] = pf[i].w;
        }
        __syncthreads();
        // issue next chunk's loads (latency hidden under compute)
        if (c < 15) {
            const int h0n = (c + 1) * 8;
#pragma unroll
            for (int i = 0; i < 4; i++) {
                int lin = i * 128 + tid;
                int t = lin >> 1, part = (lin & 1) * 4;
                pf[i] = *reinterpret_cast<const float4*>(ztb + t * 128 + h0n + part);
            }
        }
        // compute on current chunk
        const int h0 = c * 8;
#pragma unroll
        for (int hh = 0; hh < 8; ++hh) {
            const int h = h0 + hh;
            const float zl = sZL[h];
            unsigned long long w2[15];
#pragma unroll
            for (int k2 = 0; k2 < 15; k2++)
                w2[k2] = *reinterpret_cast<const unsigned long long*>(&sW[h * 32 + 2 * k2]);
#pragma unroll
            for (int tt = 0; tt < 2; tt++) {
                float zt = sZT[buf][(tid + 128 * tt) * 9 + hh];
                float z = zl + zt;
                float cc = (z > 0.f) ? z : (__expf(z) - 1.f);
                unsigned long long c2;
                asm("mov.b64 %0, {%1, %1};" : "=l"(c2) : "r"(__float_as_uint(cc)));
#pragma unroll
                for (int k2 = 0; k2 < 15; k2++)
                    asm("fma.rn.f32x2 %0, %1, %2, %0;"
                        : "+l"(acc[tt][k2]) : "l"(c2), "l"(w2[k2]));
            }
        }
        buf ^= 1;
        __syncthreads();   // all reads of old buf done before next store phase
    }

    // -------- epilogue --------
    const float plx = hlpos[bid2 * 3 + 0];
    const float ply = hlpos[bid2 * 3 + 1];
    const float plz = hlpos[bid2 * 3 + 2];
    const float pl2 = plx * plx + ply * ply + plz * plz;

#pragma unroll
    for (int tt = 0; tt < 2; tt++) {
        const int t = t0 + tid + 128 * tt;
        const int p = bid2 * 512 + t;

        float v[30];
#pragma unroll
        for (int k2 = 0; k2 < 15; k2++) {
            unsigned int ulo, uhi;
            asm("mov.b64 {%0, %1}, %2;" : "=r"(ulo), "=r"(uhi) : "l"(acc[tt][k2]));
            v[2 * k2]     = __uint_as_float(ulo) + sBias[2 * k2];
            v[2 * k2 + 1] = __uint_as_float(uhi) + sBias[2 * k2 + 1];
        }

        float m = v[0];
#pragma unroll
        for (int k = 1; k < 10; k++) m = fmaxf(m, v[k]);
        float e[10], s = 0.f;
#pragma unroll
        for (int k = 0; k < 10; k++) { e[k] = __expf(v[k] - m); s += e[k]; }
        float inv = __fdividef(1.f, s);
#pragma unroll
        for (int k = 0; k < 10; k++) out[PI_OFF + p * 10 + k] = e[k] * inv;

#pragma unroll
        for (int k = 0; k < 10; k++) {
            float x = v[10 + k];
            float r = (x > 0.f) ? x : (__expf(x) - 1.f);
            out[SIG_OFF + p * 10 + k] = r + 1.1f;
        }
#pragma unroll
        for (int k = 0; k < 10; k++) {
            float x = v[20 + k];
            float r = (x > 0.f) ? x : (__expf(x) - 1.f);
            out[MU_OFF + p * 10 + k] = r + 1.0f;
        }

        const float* pt = htpos + (b * 512 + t) * 3;
        float ptx = pt[0], pty = pt[1], ptz = pt[2];
        float d2 = -2.f * (plx * ptx + ply * pty + plz * ptz)
                 + (ptx * ptx + pty * pty + ptz * ptz) + pl2;
        out[DIST_OFF + p] = sqrtf(d2);
        out[CB_OFF + p] = (float)b;
    }
}

// ---------------- launch ----------------
extern "C" void kernel_launch(void* const* d_in, const int* in_sizes, int n_in,
                              void* d_out, int out_size)
{
    const float* hlx   = (const float*)d_in[0];
    const float* htx   = (const float*)d_in[1];
    const float* hlpos = (const float*)d_in[2];
    const float* htpos = (const float*)d_in[3];
    const void*  edge  = d_in[4];
    const float* W1    = (const float*)d_in[5];
    const float* b1    = (const float*)d_in[6];
    const float* gamma = (const float*)d_in[7];
    const float* beta  = (const float*)d_in[8];
    const float* rmean = (const float*)d_in[9];
    const float* rvar  = (const float*)d_in[10];
    const float* Wpi   = (const float*)d_in[11];
    const float* bpi   = (const float*)d_in[12];
    const float* Wsig  = (const float*)d_in[13];
    const float* bsig  = (const float*)d_in[14];
    const float* Wmu   = (const float*)d_in[15];
    const float* bmu   = (const float*)d_in[16];
    const float* Wat   = (const float*)d_in[17];
    const float* bat   = (const float*)d_in[18];
    const float* Wbd   = (const float*)d_in[19];
    const float* bbd   = (const float*)d_in[20];
    float* out = (float*)d_out;

    // hint: allow full shared-memory carveout so 4 blocks/SM fit (4 x ~35KB)
    cudaFuncSetAttribute(pair_kernel, cudaFuncAttributePreferredSharedMemoryCarveout, 100);

    prep_kernel<<<336, 256>>>(hlx, htx, edge, W1, b1, gamma, beta, rmean, rvar,
                              Wat, bat, Wbd, bbd, out);
    pair_kernel<<<1024, 128>>>(hlpos, htpos, Wpi, bpi, Wsig, bsig, Wmu, bmu, out);
}

// round 5
// speedup vs baseline: 1.5765x; 1.2305x over previous
#include <cuda_runtime.h>
#include <cstdint>

// ---------------- problem constants ----------------
#define BB 8
#define NL 64
#define NT 512
#define CF 128
#define HH 128
#define KK 10
#define EE 1024
#define BN_EPS 1e-4f

#define PI_OFF   0
#define SIG_OFF  2621440
#define MU_OFF   5242880
#define DIST_OFF 7864320
#define ATOM_OFF 8126464
#define BOND_OFF 8140800
#define CB_OFF   8146944

// ---------------- scratch ----------------
__device__ float g_ZL[512 * 128];        // (b*NL+l, h)       : zl*s
__device__ float g_ZTt[128 * 4096];      // [h][b*512+t]      : zt*s + (b1-mu)*s + beta  (TRANSPOSED)

// ================= prep kernel: gemm1 (blocks 0..143), bond (144..271), atom (272..335) =================
__global__ void __launch_bounds__(256)
prep_kernel(const float* __restrict__ hlx, const float* __restrict__ htx,
            const void*  __restrict__ edge,
            const float* __restrict__ W1,  const float* __restrict__ b1,
            const float* __restrict__ gamma, const float* __restrict__ beta,
            const float* __restrict__ rmean, const float* __restrict__ rvar,
            const float* __restrict__ Wat, const float* __restrict__ bat,
            const float* __restrict__ Wbd, const float* __restrict__ bbd,
            float* __restrict__ out)
{
    __shared__ __align__(16) char s_buf[20800];
    const int tid = threadIdx.x;

    if (blockIdx.x < 144) {
        // ---------- GEMM1: ZL/ZT with BN folding ----------
        float (*sX)[33]   = reinterpret_cast<float(*)[33]>(s_buf);                 // 32x33
        float (*sWt)[128] = reinterpret_cast<float(*)[128]>(s_buf + 32*33*4);      // 32x128

        const int row0 = blockIdx.x * 32;
        const bool isL = (row0 < 512);
        const float* X   = isL ? hlx : htx;
        const int    xr0 = isL ? row0 : row0 - 512;
        const float* Wh  = W1 + (isL ? 0 : 128 * 128);

        const int tx = tid & 15, ty = tid >> 4;

        float acc[2][8];
#pragma unroll
        for (int i = 0; i < 2; i++)
#pragma unroll
            for (int j = 0; j < 8; j++) acc[i][j] = 0.f;

        for (int k0 = 0; k0 < 128; k0 += 32) {
            __syncthreads();
            {
                int idx = tid * 4;
                int r = idx >> 5, c = idx & 31;
                float4 v = *reinterpret_cast<const float4*>(X + (xr0 + r) * 128 + k0 + c);
                sX[r][c] = v.x; sX[r][c + 1] = v.y; sX[r][c + 2] = v.z; sX[r][c + 3] = v.w;
            }
#pragma unroll
            for (int j = 0; j < 16; j++) {
                int idx = tid + 256 * j;
                int r = idx >> 7, c = idx & 127;
                sWt[r][c] = Wh[(k0 + r) * 128 + c];
            }
            __syncthreads();
#pragma unroll
            for (int ck = 0; ck < 32; ++ck) {
                float x0 = sX[ty * 2][ck];
                float x1 = sX[ty * 2 + 1][ck];
#pragma unroll
                for (int j = 0; j < 8; j++) {
                    float w = sWt[ck][tx + 16 * j];
                    acc[0][j] += x0 * w;
                    acc[1][j] += x1 * w;
                }
            }
        }

        if (isL) {
            // ZL stays row-major
#pragma unroll
            for (int j = 0; j < 8; j++) {
                int h = tx + 16 * j;
                float s   = gamma[h] * rsqrtf(rvar[h] + BN_EPS);
#pragma unroll
                for (int i = 0; i < 2; i++) {
                    int r = row0 + ty * 2 + i;
                    g_ZL[r * 128 + h] = acc[i][j] * s;
                }
            }
        } else {
            // ZT: BN fold + transpose through shared, write [h][n] coalesced
            float* sT = reinterpret_cast<float*>(s_buf);    // [32][129]
            __syncthreads();   // done with sX/sWt
#pragma unroll
            for (int j = 0; j < 8; j++) {
                int h = tx + 16 * j;
                float s   = gamma[h] * rsqrtf(rvar[h] + BN_EPS);
                float off = (b1[h] - rmean[h]) * s + beta[h];
#pragma unroll
                for (int i = 0; i < 2; i++) {
                    int rr = ty * 2 + i;
                    sT[rr * 129 + h] = acc[i][j] * s + off;
                }
            }
            __syncthreads();
            const int n0 = row0 - 512;
#pragma unroll
            for (int it = 0; it < 16; it++) {
                int idx = tid + it * 256;          // 0..4095
                int h = idx >> 5, rr = idx & 31;
                g_ZTt[h * 4096 + n0 + rr] = sT[rr * 129 + h];
            }
        }
    } else if (blockIdx.x < 272) {
        // ---------- BOND: warp per edge, block-local dtype detection ----------
        int* s_is64 = reinterpret_cast<int*>(s_buf);
        if (tid == 0) *s_is64 = 1;
        __syncthreads();
        const int* p32 = reinterpret_cast<const int*>(edge);
        if (p32[2 * tid + 1] != 0) *s_is64 = 0;
        __syncthreads();
        const int is64 = *s_is64;

        const int wid = tid >> 5, lane = tid & 31;
        const int e = (blockIdx.x - 144) * 8 + wid;
        int src, dst;
        if (is64) {
            const long long* p = reinterpret_cast<const long long*>(edge);
            src = (int)p[e]; dst = (int)p[EE + e];
        } else {
            src = p32[e]; dst = p32[EE + e];
        }
        float4 xs = *reinterpret_cast<const float4*>(hlx + src * 128 + lane * 4);
        float4 xd = *reinterpret_cast<const float4*>(hlx + dst * 128 + lane * 4);
        float acc[6];
#pragma unroll
        for (int j = 0; j < 6; j++) acc[j] = 0.f;
        const float* xsv = reinterpret_cast<const float*>(&xs);
        const float* xdv = reinterpret_cast<const float*>(&xd);
#pragma unroll
        for (int i = 0; i < 4; i++) {
            int c = lane * 4 + i;
#pragma unroll
            for (int j = 0; j < 6; j++) {
                acc[j] += xsv[i] * __ldg(Wbd + c * 6 + j);
                acc[j] += xdv[i] * __ldg(Wbd + (128 + c) * 6 + j);
            }
        }
#pragma unroll
        for (int off = 16; off > 0; off >>= 1)
#pragma unroll
            for (int j = 0; j < 6; j++)
                acc[j] += __shfl_down_sync(0xffffffffu, acc[j], off);
        if (lane == 0) {
#pragma unroll
            for (int j = 0; j < 6; j++)
                out[BOND_OFF + e * 6 + j] = acc[j] + bbd[j];
        }
    } else {
        // ---------- ATOM: 8 rows per block, shared transposed Wat ----------
        float* sWat = reinterpret_cast<float*>(s_buf);          // [28][129]
        float* sX   = sWat + 28 * 129;                          // [8][128]
        const int aid = blockIdx.x - 272;                       // 0..63
        const int row0 = aid * 8;

        for (int idx = tid; idx < 128 * 28; idx += 256) {
            int c = idx / 28;
            int k = idx - c * 28;
            sWat[k * 129 + c] = Wat[idx];
        }
        for (int idx = tid; idx < 8 * 128; idx += 256) {
            sX[idx] = hlx[row0 * 128 + idx];
        }
        __syncthreads();

        const int r = tid >> 5, k = tid & 31;
        if (k < 28) {
            float acc = bat[k];
            const float* xr = sX + r * 128;
            const float* wr = sWat + k * 129;
#pragma unroll 8
            for (int c = 0; c < 128; c++) acc += xr[c] * wr[c];
            out[ATOM_OFF + (row0 + r) * 28 + k] = acc;
        }
    }
}

// ================= pair kernel =================
// grid = 1024: block = (b*64+l, half), 128 threads, tt=2 (t = half*256+tid+128*tt).
// zt loaded DIRECTLY from transposed g_ZTt (coalesced LDG.32, L2-resident) with
// software-pipelined prefetch; weights via LDS.128; no barriers in main loop.
__global__ void __launch_bounds__(128, 4)
pair_kernel(const float* __restrict__ hlpos, const float* __restrict__ htpos,
            const float* __restrict__ Wpi,  const float* __restrict__ bpi,
            const float* __restrict__ Wsig, const float* __restrict__ bsig,
            const float* __restrict__ Wmu,  const float* __restrict__ bmu,
            float* __restrict__ out)
{
    __shared__ __align__(16) float sW[128 * 32]; // [h][j], j: 0-9 Wpi, 10-19 Wsig, 20-29 Wmu, 30/31 pad
    __shared__ float sBias[32];
    __shared__ float sZL[128];

    const int tid = threadIdx.x;
    const int bid2 = blockIdx.x >> 1;       // = b*64 + l
    const int half = blockIdx.x & 1;
    const int b = bid2 >> 6;
    const int t0 = half * 256;

#pragma unroll
    for (int j = 0; j < 32; j++) {
        float w;
        if (j < 10)      w = Wpi [tid * 10 + j];
        else if (j < 20) w = Wsig[tid * 10 + (j - 10)];
        else if (j < 30) w = Wmu [tid * 10 + (j - 20)];
        else             w = 0.f;
        sW[tid * 32 + j] = w;
    }
    if (tid < 32) {
        float bv;
        if (tid < 10)      bv = bpi [tid];
        else if (tid < 20) bv = bsig[tid - 10];
        else if (tid < 30) bv = bmu [tid - 20];
        else               bv = 0.f;
        sBias[tid] = bv;
    }
    sZL[tid] = g_ZL[bid2 * 128 + tid];
    __syncthreads();

    unsigned long long acc[2][15];
#pragma unroll
    for (int tt = 0; tt < 2; tt++)
#pragma unroll
        for (int k2 = 0; k2 < 15; k2++) acc[tt][k2] = 0ull;

    const float* ztb = g_ZTt + b * 512 + t0 + tid;   // per-thread column base

    // ---- prologue: chunk 0 loads + ELU ----
    float cc[2][8];
    {
        float zt[2][8];
#pragma unroll
        for (int hh = 0; hh < 8; hh++)
#pragma unroll
            for (int tt = 0; tt < 2; tt++)
                zt[tt][hh] = ztb[hh * 4096 + tt * 128];
#pragma unroll
        for (int hh = 0; hh < 8; hh++) {
            float zl = sZL[hh];
#pragma unroll
            for (int tt = 0; tt < 2; tt++) {
                float z = zl + zt[tt][hh];
                cc[tt][hh] = (z > 0.f) ? z : (__expf(z) - 1.f);
            }
        }
    }

    union WU { float4 v; unsigned long long u[2]; };

    for (int c = 0; c < 16; c++) {
        // issue next chunk's loads early (latency hidden under FMA sweep)
        float ztn[2][8];
        if (c < 15) {
            const float* zp = ztb + (c + 1) * 8 * 4096;
#pragma unroll
            for (int hh = 0; hh < 8; hh++)
#pragma unroll
                for (int tt = 0; tt < 2; tt++)
                    ztn[tt][hh] = zp[hh * 4096 + tt * 128];
        }
        // ---- FMA sweep over current chunk ----
#pragma unroll
        for (int hh = 0; hh < 8; hh++) {
            const float4* w4 = reinterpret_cast<const float4*>(sW + (c * 8 + hh) * 32);
            WU w[8];
#pragma unroll
            for (int i = 0; i < 8; i++) w[i].v = w4[i];
#pragma unroll
            for (int tt = 0; tt < 2; tt++) {
                unsigned long long c2;
                asm("mov.b64 %0, {%1, %1};" : "=l"(c2) : "r"(__float_as_uint(cc[tt][hh])));
#pragma unroll
                for (int k2 = 0; k2 < 15; k2++)
                    asm("fma.rn.f32x2 %0, %1, %2, %0;"
                        : "+l"(acc[tt][k2]) : "l"(c2), "l"(w[k2 >> 1].u[k2 & 1]));
            }
        }
        // ---- ELU for next chunk ----
        if (c < 15) {
#pragma unroll
            for (int hh = 0; hh < 8; hh++) {
                float zl = sZL[(c + 1) * 8 + hh];
#pragma unroll
                for (int tt = 0; tt < 2; tt++) {
                    float z = zl + ztn[tt][hh];
                    cc[tt][hh] = (z > 0.f) ? z : (__expf(z) - 1.f);
                }
            }
        }
    }

    // -------- epilogue --------
    const float plx = hlpos[bid2 * 3 + 0];
    const float ply = hlpos[bid2 * 3 + 1];
    const float plz = hlpos[bid2 * 3 + 2];
    const float pl2 = plx * plx + ply * ply + plz * plz;

#pragma unroll
    for (int tt = 0; tt < 2; tt++) {
        const int t = t0 + tid + 128 * tt;
        const int p = bid2 * 512 + t;

        float v[30];
#pragma unroll
        for (int k2 = 0; k2 < 15; k2++) {
            unsigned int ulo, uhi;
            asm("mov.b64 {%0, %1}, %2;" : "=r"(ulo), "=r"(uhi) : "l"(acc[tt][k2]));
            v[2 * k2]     = __uint_as_float(ulo) + sBias[2 * k2];
            v[2 * k2 + 1] = __uint_as_float(uhi) + sBias[2 * k2 + 1];
        }

        float m = v[0];
#pragma unroll
        for (int k = 1; k < 10; k++) m = fmaxf(m, v[k]);
        float e[10], s = 0.f;
#pragma unroll
        for (int k = 0; k < 10; k++) { e[k] = __expf(v[k] - m); s += e[k]; }
        float inv = __fdividef(1.f, s);
#pragma unroll
        for (int k = 0; k < 10; k++) out[PI_OFF + p * 10 + k] = e[k] * inv;

#pragma unroll
        for (int k = 0; k < 10; k++) {
            float x = v[10 + k];
            float r = (x > 0.f) ? x : (__expf(x) - 1.f);
            out[SIG_OFF + p * 10 + k] = r + 1.1f;
        }
#pragma unroll
        for (int k = 0; k < 10; k++) {
            float x = v[20 + k];
            float r = (x > 0.f) ? x : (__expf(x) - 1.f);
            out[MU_OFF + p * 10 + k] = r + 1.0f;
        }

        const float* pt = htpos + (b * 512 + t) * 3;
        float ptx = pt[0], pty = pt[1], ptz = pt[2];
        float d2 = -2.f * (plx * ptx + ply * pty + plz * ptz)
                 + (ptx * ptx + pty * pty + ptz * ptz) + pl2;
        out[DIST_OFF + p] = sqrtf(d2);
        out[CB_OFF + p] = (float)b;
    }
}

// ---------------- launch ----------------
extern "C" void kernel_launch(void* const* d_in, const int* in_sizes, int n_in,
                              void* d_out, int out_size)
{
    const float* hlx   = (const float*)d_in[0];
    const float* htx   = (const float*)d_in[1];
    const float* hlpos = (const float*)d_in[2];
    const float* htpos = (const float*)d_in[3];
    const void*  edge  = d_in[4];
    const float* W1    = (const float*)d_in[5];
    const float* b1    = (const float*)d_in[6];
    const float* gamma = (const float*)d_in[7];
    const float* beta  = (const float*)d_in[8];
    const float* rmean = (const float*)d_in[9];
    const float* rvar  = (const float*)d_in[10];
    const float* Wpi   = (const float*)d_in[11];
    const float* bpi   = (const float*)d_in[12];
    const float* Wsig  = (const float*)d_in[13];
    const float* bsig  = (const float*)d_in[14];
    const float* Wmu   = (const float*)d_in[15];
    const float* bmu   = (const float*)d_in[16];
    const float* Wat   = (const float*)d_in[17];
    const float* bat   = (const float*)d_in[18];
    const float* Wbd   = (const float*)d_in[19];
    const float* bbd   = (const float*)d_in[20];
    float* out = (float*)d_out;

    prep_kernel<<<336, 256>>>(hlx, htx, edge, W1, b1, gamma, beta, rmean, rvar,
                              Wat, bat, Wbd, bbd, out);
    pair_kernel<<<1024, 128>>>(hlpos, htpos, Wpi, bpi, Wsig, bsig, Wmu, bmu, out);
}

// round 9
// speedup vs baseline: 1.7299x; 1.0973x over previous
#include <cuda_runtime.h>
#include <cuda_bf16.h>
#include <cstdint>

// ---------------- problem constants ----------------
#define BB 8
#define NL 64
#define NT 512
#define CF 128
#define HH 128
#define KK 10
#define EE 1024
#define BN_EPS 1e-4f

#define PI_OFF   0
#define SIG_OFF  2621440
#define MU_OFF   5242880
#define DIST_OFF 7864320
#define ATOM_OFF 8126464
#define BOND_OFF 8140800
#define CB_OFF   8146944

// ---------------- scratch ----------------
__device__ float g_ZL[512 * 128];        // (b*NL+l, h) : zl*s
__device__ float g_ZTt[128 * 4096];      // [h][b*512+t]: zt*s + (b1-mu)*s + beta  (transposed)
__device__ unsigned short g_Bhi[4096];   // W^T [n=0..31][k=0..127] bf16 hi, linear n*128+k
__device__ unsigned short g_Blo[4096];   // lo part

// ---------------- shared layout of pair kernel (dynamic) ----------------
// per-warp A slice: 32 rows x 144B (64 bf16 + pad), hi then lo
#define AW_STRIDE   144
#define AW_HALFSZ   (32 * AW_STRIDE)       // 4608
#define AW_SIZE     (2 * AW_HALFSZ)        // 9216 per warp
#define SB_HI       (4 * AW_SIZE)          // 36864
#define SB_STRIDE   272
#define SB_LO       (SB_HI + 32 * SB_STRIDE)   // 45568
#define SZL_OFF     (SB_LO + 32 * SB_STRIDE)   // 54272
#define SBIAS_OFF   (SZL_OFF + 512)            // 54784
#define SMEM_TOTAL  (SBIAS_OFF + 128)          // 54912
#define SD_STRIDE   136

__device__ __forceinline__ uint32_t smem_to_u32(const void* p) {
    uint32_t a;
    asm("{ .reg .u64 t; cvta.to.shared.u64 t, %1; cvt.u32.u64 %0, t; }" : "=r"(a) : "l"(p));
    return a;
}
__device__ __forceinline__ void ldsm4(uint32_t* r, uint32_t addr) {
    asm volatile("ldmatrix.sync.aligned.m8n8.x4.shared.b16 {%0,%1,%2,%3}, [%4];"
        : "=r"(r[0]), "=r"(r[1]), "=r"(r[2]), "=r"(r[3]) : "r"(addr));
}
__device__ __forceinline__ void mma16816(float* d, const uint32_t* a, uint32_t b0, uint32_t b1) {
    asm volatile("mma.sync.aligned.m16n8k16.row.col.f32.bf16.bf16.f32 "
        "{%0,%1,%2,%3}, {%4,%5,%6,%7}, {%8,%9}, {%0,%1,%2,%3};"
        : "+f"(d[0]), "+f"(d[1]), "+f"(d[2]), "+f"(d[3])
        : "r"(a[0]), "r"(a[1]), "r"(a[2]), "r"(a[3]), "r"(b0), "r"(b1));
}

// ================= prep kernel =================
// blocks 0..143 gemm1, 144..271 bond, 272..335 atom, 336 B-build
__global__ void __launch_bounds__(256)
prep_kernel(const float* __restrict__ hlx, const float* __restrict__ htx,
            const void*  __restrict__ edge,
            const float* __restrict__ W1,  const float* __restrict__ b1,
            const float* __restrict__ gamma, const float* __restrict__ beta,
            const float* __restrict__ rmean, const float* __restrict__ rvar,
            const float* __restrict__ Wat, const float* __restrict__ bat,
            const float* __restrict__ Wbd, const float* __restrict__ bbd,
            const float* __restrict__ Wpi, const float* __restrict__ Wsig,
            const float* __restrict__ Wmu,
            float* __restrict__ out)
{
    __shared__ __align__(16) char s_buf[20800];
    const int tid = threadIdx.x;

    if (blockIdx.x < 144) {
        float (*sX)[33]   = reinterpret_cast<float(*)[33]>(s_buf);
        float (*sWt)[128] = reinterpret_cast<float(*)[128]>(s_buf + 32*33*4);

        const int row0 = blockIdx.x * 32;
        const bool isL = (row0 < 512);
        const float* X   = isL ? hlx : htx;
        const int    xr0 = isL ? row0 : row0 - 512;
        const float* Wh  = W1 + (isL ? 0 : 128 * 128);
        const int tx = tid & 15, ty = tid >> 4;

        float acc[2][8];
#pragma unroll
        for (int i = 0; i < 2; i++)
#pragma unroll
            for (int j = 0; j < 8; j++) acc[i][j] = 0.f;

        for (int k0 = 0; k0 < 128; k0 += 32) {
            __syncthreads();
            {
                int idx = tid * 4;
                int r = idx >> 5, c = idx & 31;
                float4 v = *reinterpret_cast<const float4*>(X + (xr0 + r) * 128 + k0 + c);
                sX[r][c] = v.x; sX[r][c+1] = v.y; sX[r][c+2] = v.z; sX[r][c+3] = v.w;
            }
#pragma unroll
            for (int j = 0; j < 16; j++) {
                int idx = tid + 256 * j;
                int r = idx >> 7, c = idx & 127;
                sWt[r][c] = Wh[(k0 + r) * 128 + c];
            }
            __syncthreads();
#pragma unroll
            for (int ck = 0; ck < 32; ++ck) {
                float x0 = sX[ty*2][ck], x1 = sX[ty*2+1][ck];
#pragma unroll
                for (int j = 0; j < 8; j++) {
                    float w = sWt[ck][tx + 16*j];
                    acc[0][j] += x0 * w;
                    acc[1][j] += x1 * w;
                }
            }
        }

        if (isL) {
#pragma unroll
            for (int j = 0; j < 8; j++) {
                int h = tx + 16*j;
                float s = gamma[h] * rsqrtf(rvar[h] + BN_EPS);
#pragma unroll
                for (int i = 0; i < 2; i++)
                    g_ZL[(row0 + ty*2 + i) * 128 + h] = acc[i][j] * s;
            }
        } else {
            float* sT = reinterpret_cast<float*>(s_buf);   // [32][129]
            __syncthreads();
#pragma unroll
            for (int j = 0; j < 8; j++) {
                int h = tx + 16*j;
                float s   = gamma[h] * rsqrtf(rvar[h] + BN_EPS);
                float off = (b1[h] - rmean[h]) * s + beta[h];
#pragma unroll
                for (int i = 0; i < 2; i++)
                    sT[(ty*2 + i) * 129 + h] = acc[i][j] * s + off;
            }
            __syncthreads();
            const int n0 = row0 - 512;
#pragma unroll
            for (int it = 0; it < 16; it++) {
                int idx = tid + it * 256;
                int h = idx >> 5, rr = idx & 31;
                g_ZTt[h * 4096 + n0 + rr] = sT[rr * 129 + h];
            }
        }
    } else if (blockIdx.x < 272) {
        int* s_is64 = reinterpret_cast<int*>(s_buf);
        if (tid == 0) *s_is64 = 1;
        __syncthreads();
        const int* p32 = reinterpret_cast<const int*>(edge);
        if (p32[2*tid + 1] != 0) *s_is64 = 0;
        __syncthreads();
        const int is64 = *s_is64;

        const int wid = tid >> 5, lane = tid & 31;
        const int e = (blockIdx.x - 144) * 8 + wid;
        int src, dst;
        if (is64) {
            const long long* p = reinterpret_cast<const long long*>(edge);
            src = (int)p[e]; dst = (int)p[EE + e];
        } else {
            src = p32[e]; dst = p32[EE + e];
        }
        float4 xs = *reinterpret_cast<const float4*>(hlx + src * 128 + lane * 4);
        float4 xd = *reinterpret_cast<const float4*>(hlx + dst * 128 + lane * 4);
        float acc[6];
#pragma unroll
        for (int j = 0; j < 6; j++) acc[j] = 0.f;
        const float* xsv = reinterpret_cast<const float*>(&xs);
        const float* xdv = reinterpret_cast<const float*>(&xd);
#pragma unroll
        for (int i = 0; i < 4; i++) {
            int c = lane * 4 + i;
#pragma unroll
            for (int j = 0; j < 6; j++) {
                acc[j] += xsv[i] * __ldg(Wbd + c * 6 + j);
                acc[j] += xdv[i] * __ldg(Wbd + (128 + c) * 6 + j);
            }
        }
#pragma unroll
        for (int off = 16; off > 0; off >>= 1)
#pragma unroll
            for (int j = 0; j < 6; j++)
                acc[j] += __shfl_down_sync(0xffffffffu, acc[j], off);
        if (lane == 0)
#pragma unroll
            for (int j = 0; j < 6; j++)
                out[BOND_OFF + e * 6 + j] = acc[j] + bbd[j];
    } else if (blockIdx.x < 336) {
        float* sWat = reinterpret_cast<float*>(s_buf);      // [28][129]
        float* sX   = sWat + 28 * 129;                      // [8][128]
        const int row0 = (blockIdx.x - 272) * 8;

        for (int idx = tid; idx < 128 * 28; idx += 256) {
            int c = idx / 28, k = idx - c * 28;
            sWat[k * 129 + c] = Wat[idx];
        }
        for (int idx = tid; idx < 8 * 128; idx += 256)
            sX[idx] = hlx[row0 * 128 + idx];
        __syncthreads();

        const int r = tid >> 5, k = tid & 31;
        if (k < 28) {
            float acc = bat[k];
            const float* xr = sX + r * 128;
            const float* wr = sWat + k * 129;
#pragma unroll 8
            for (int c = 0; c < 128; c++) acc += xr[c] * wr[c];
            out[ATOM_OFF + (row0 + r) * 28 + k] = acc;
        }
    } else {
        // ---------- B-build: W^T [n][k] bf16 hi/lo, linear n*128+k ----------
#pragma unroll
        for (int i = 0; i < 16; i++) {
            int idx = tid + 256 * i;       // 0..4095
            int n = idx >> 7, k = idx & 127;
            float w = 0.f;
            if (n < 10)      w = Wpi [k * 10 + n];
            else if (n < 20) w = Wsig[k * 10 + (n - 10)];
            else if (n < 30) w = Wmu [k * 10 + (n - 20)];
            __nv_bfloat16 bh = __float2bfloat16(w);
            __nv_bfloat16 bl = __float2bfloat16(w - __bfloat162float(bh));
            g_Bhi[idx] = __bfloat16_as_ushort(bh);
            g_Blo[idx] = __bfloat16_as_ushort(bl);
        }
    }
}

// ================= pair kernel: HMMA (mma.sync bf16) =================
// grid 2048 = (b*64+l) x 4 t-tiles of 128. 128 threads.
// Warp w owns rows w*32..w*32+31 end-to-end: produce A (elu bf16 hi/lo) into its
// own padded smem slice, ldmatrix + 3-term mma.sync, D back via slice, epilogue.
__global__ void __launch_bounds__(128)
pair_hmma_kernel(const float* __restrict__ hlpos, const float* __restrict__ htpos,
                 const float* __restrict__ bpi, const float* __restrict__ bsig,
                 const float* __restrict__ bmu, float* __restrict__ out)
{
    extern __shared__ __align__(16) char sm[];
    const uint32_t smb = smem_to_u32(sm);
    const int tid  = threadIdx.x;
    const int w    = tid >> 5;
    const int lane = tid & 31;
    const int g    = lane >> 2, tg = lane & 3;

    const int bid  = blockIdx.x;
    const int bid2 = bid >> 2;          // b*64 + l
    const int tile = bid & 3;
    const int b    = bid2 >> 6;
    const int n0   = b * 512 + tile * 128;

    float* sZL   = reinterpret_cast<float*>(sm + SZL_OFF);
    float* sBias = reinterpret_cast<float*>(sm + SBIAS_OFF);

    // ---- block init: B tiles, zL, bias ----
#pragma unroll
    for (int i = 0; i < 32; i++) {
        int idx = tid + 128 * i;         // 0..4095
        int n = idx >> 7, k = idx & 127;
        *reinterpret_cast<unsigned short*>(sm + SB_HI + n * SB_STRIDE + 2 * k) = g_Bhi[idx];
        *reinterpret_cast<unsigned short*>(sm + SB_LO + n * SB_STRIDE + 2 * k) = g_Blo[idx];
    }
    sZL[tid] = g_ZL[bid2 * 128 + tid];
    if (tid < 32) {
        float bv = 0.f;
        if (tid < 10)      bv = bpi [tid];
        else if (tid < 20) bv = bsig[tid - 10];
        else if (tid < 30) bv = bmu [tid - 20];
        sBias[tid] = bv;
    }
    __syncthreads();

    const int aw_off = w * AW_SIZE;               // this warp's A slice (byte offset)
    const float* ztcol = g_ZTt + n0 + tid;        // this thread's column of ZTt

    // ldmatrix per-lane address pieces: lanes 0-15 -> rows, +16 -> k+8 (16B)
    const int lr = lane & 15;
    const int lkb = (lane >> 4) * 16;

    float d[2][4][4];
#pragma unroll
    for (int ms = 0; ms < 2; ms++)
#pragma unroll
        for (int ns = 0; ns < 4; ns++)
#pragma unroll
            for (int i = 0; i < 4; i++) d[ms][ns][i] = 0.f;

    for (int half = 0; half < 2; half++) {
        // ---- phase 1: produce A hi/lo rows (this warp's 32 rows = its own threads) ----
#pragma unroll
        for (int c16 = 0; c16 < 4; c16++) {
            const int hb = half * 64 + c16 * 16;
            float z[16];
#pragma unroll
            for (int i = 0; i < 16; i++) z[i] = ztcol[(hb + i) * 4096];
            uint32_t hi_u[8], lo_u[8];
#pragma unroll
            for (int j = 0; j < 8; j++) {
                float z0 = z[2*j]     + sZL[hb + 2*j];
                float z1 = z[2*j + 1] + sZL[hb + 2*j + 1];
                float c0 = (z0 > 0.f) ? z0 : (__expf(z0) - 1.f);
                float c1 = (z1 > 0.f) ? z1 : (__expf(z1) - 1.f);
                __nv_bfloat162 bh = __floats2bfloat162_rn(c0, c1);
                uint32_t u = *reinterpret_cast<uint32_t*>(&bh);
                float f0 = __uint_as_float(u << 16);
                float f1 = __uint_as_float(u & 0xffff0000u);
                __nv_bfloat162 bl = __floats2bfloat162_rn(c0 - f0, c1 - f1);
                hi_u[j] = u;
                lo_u[j] = *reinterpret_cast<uint32_t*>(&bl);
            }
            const int off = aw_off + lane * AW_STRIDE + c16 * 32;
            *reinterpret_cast<uint4*>(sm + off)      = make_uint4(hi_u[0], hi_u[1], hi_u[2], hi_u[3]);
            *reinterpret_cast<uint4*>(sm + off + 16) = make_uint4(hi_u[4], hi_u[5], hi_u[6], hi_u[7]);
            *reinterpret_cast<uint4*>(sm + off + AW_HALFSZ)      = make_uint4(lo_u[0], lo_u[1], lo_u[2], lo_u[3]);
            *reinterpret_cast<uint4*>(sm + off + AW_HALFSZ + 16) = make_uint4(lo_u[4], lo_u[5], lo_u[6], lo_u[7]);
        }
        __syncwarp();

        // ---- phase 2: MMA over this K-half (4 k16 steps) ----
#pragma unroll
        for (int ks = 0; ks < 4; ks++) {
            uint32_t ahi[2][4], alo[2][4];
#pragma unroll
            for (int ms = 0; ms < 2; ms++) {
                uint32_t addr = smb + aw_off + (ms * 16 + lr) * AW_STRIDE + ks * 32 + lkb;
                ldsm4(ahi[ms], addr);
                ldsm4(alo[ms], addr + AW_HALFSZ);
            }
#pragma unroll
            for (int ns = 0; ns < 4; ns++) {
                const int boff = (ns * 8 + g) * SB_STRIDE + (half * 64 + ks * 16 + tg * 2) * 2;
                uint32_t bh0 = *reinterpret_cast<const uint32_t*>(sm + SB_HI + boff);
                uint32_t bh1 = *reinterpret_cast<const uint32_t*>(sm + SB_HI + boff + 16);
                uint32_t bl0 = *reinterpret_cast<const uint32_t*>(sm + SB_LO + boff);
                uint32_t bl1 = *reinterpret_cast<const uint32_t*>(sm + SB_LO + boff + 16);
#pragma unroll
                for (int ms = 0; ms < 2; ms++) {
                    mma16816(d[ms][ns], ahi[ms], bh0, bh1);
                    mma16816(d[ms][ns], alo[ms], bh0, bh1);
                    mma16816(d[ms][ns], ahi[ms], bl0, bl1);
                }
            }
        }
        __syncwarp();   // A slice free for next half
    }

    // ---- D -> warp's smem slice (row-major, stride 136B) ----
#pragma unroll
    for (int ms = 0; ms < 2; ms++)
#pragma unroll
        for (int ns = 0; ns < 4; ns++) {
            int r0 = ms * 16 + g;
            int cb = (ns * 8 + tg * 2) * 4;
            *reinterpret_cast<float2*>(sm + aw_off + r0 * SD_STRIDE + cb) =
                make_float2(d[ms][ns][0], d[ms][ns][1]);
            *reinterpret_cast<float2*>(sm + aw_off + (r0 + 8) * SD_STRIDE + cb) =
                make_float2(d[ms][ns][2], d[ms][ns][3]);
        }
    __syncwarp();

    // ---- epilogue: thread owns pair row = tid ----
    {
        const int t = tile * 128 + tid;
        const int p = bid2 * 512 + t;
        const char* drow = sm + aw_off + lane * SD_STRIDE;

        float v[30];
#pragma unroll
        for (int k = 0; k < 30; k++)
            v[k] = *reinterpret_cast<const float*>(drow + k * 4) + sBias[k];

        float m = v[0];
#pragma unroll
        for (int k = 1; k < 10; k++) m = fmaxf(m, v[k]);
        float e[10], s = 0.f;
#pragma unroll
        for (int k = 0; k < 10; k++) { e[k] = __expf(v[k] - m); s += e[k]; }
        float inv = __fdividef(1.f, s);
#pragma unroll
        for (int k = 0; k < 10; k++) out[PI_OFF + p * 10 + k] = e[k] * inv;

#pragma unroll
        for (int k = 0; k < 10; k++) {
            float x = v[10 + k];
            float r = (x > 0.f) ? x : (__expf(x) - 1.f);
            out[SIG_OFF + p * 10 + k] = r + 1.1f;
        }
#pragma unroll
        for (int k = 0; k < 10; k++) {
            float x = v[20 + k];
            float r = (x > 0.f) ? x : (__expf(x) - 1.f);
            out[MU_OFF + p * 10 + k] = r + 1.0f;
        }

        const float plx = hlpos[bid2 * 3 + 0];
        const float ply = hlpos[bid2 * 3 + 1];
        const float plz = hlpos[bid2 * 3 + 2];
        const float* pt = htpos + (b * 512 + t) * 3;
        float d2 = -2.f * (plx * pt[0] + ply * pt[1] + plz * pt[2])
                 + (pt[0]*pt[0] + pt[1]*pt[1] + pt[2]*pt[2])
                 + (plx*plx + ply*ply + plz*plz);
        out[DIST_OFF + p] = sqrtf(d2);
        out[CB_OFF + p] = (float)b;
    }
}

// ---------------- launch ----------------
extern "C" void kernel_launch(void* const* d_in, const int* in_sizes, int n_in,
                              void* d_out, int out_size)
{
    const float* hlx   = (const float*)d_in[0];
    const float* htx   = (const float*)d_in[1];
    const float* hlpos = (const float*)d_in[2];
    const float* htpos = (const float*)d_in[3];
    const void*  edge  = d_in[4];
    const float* W1    = (const float*)d_in[5];
    const float* b1    = (const float*)d_in[6];
    const float* gamma = (const float*)d_in[7];
    const float* beta  = (const float*)d_in[8];
    const float* rmean = (const float*)d_in[9];
    const float* rvar  = (const float*)d_in[10];
    const float* Wpi   = (const float*)d_in[11];
    const float* bpi   = (const float*)d_in[12];
    const float* Wsig  = (const float*)d_in[13];
    const float* bsig  = (const float*)d_in[14];
    const float* Wmu   = (const float*)d_in[15];
    const float* bmu   = (const float*)d_in[16];
    const float* Wat   = (const float*)d_in[17];
    const float* bat   = (const float*)d_in[18];
    const float* Wbd   = (const float*)d_in[19];
    const float* bbd   = (const float*)d_in[20];
    float* out = (float*)d_out;

    cudaFuncSetAttribute(pair_hmma_kernel, cudaFuncAttributeMaxDynamicSharedMemorySize, SMEM_TOTAL);

    prep_kernel<<<337, 256>>>(hlx, htx, edge, W1, b1, gamma, beta, rmean, rvar,
                              Wat, bat, Wbd, bbd, Wpi, Wsig, Wmu, out);
    pair_hmma_kernel<<<2048, 128, SMEM_TOTAL>>>(hlpos, htpos, bpi, bsig, bmu, out);
}

// round 13
// speedup vs baseline: 1.7715x; 1.0241x over previous
#include <cuda_runtime.h>
#include <cuda_bf16.h>
#include <cstdint>

// ---------------- problem constants ----------------
#define BB 8
#define NL 64
#define NT 512
#define CF 128
#define HH 128
#define KK 10
#define EE 1024
#define BN_EPS 1e-4f

#define PI_OFF   0
#define SIG_OFF  2621440
#define MU_OFF   5242880
#define DIST_OFF 7864320
#define ATOM_OFF 8126464
#define BOND_OFF 8140800
#define CB_OFF   8146944

// ---------------- scratch ----------------
__device__ float g_ZL[512 * 128];        // (b*NL+l, h) : zl*s
__device__ float g_ZTt[128 * 4096];      // [h][b*512+t]: zt*s + (b1-mu)*s + beta  (transposed)
__device__ uint4 g_Bfrag[1024];          // [half][ks][ns][lane] = {bh0, bh1, bl0, bl1}

// ---------------- shared layout of pair kernel (dynamic) ----------------
#define SBF       0                       // B fragments, 16384 B
#define SD_OFF    16384                   // per-warp D writeback: 32 rows x 132B
#define SD_WARP   4224
#define SZL_OFF   (16384 + 4 * SD_WARP)   // 33280
#define SBIAS_OFF (SZL_OFF + 512)         // 33792
#define SMEM_TOTAL (SBIAS_OFF + 128)      // 33920

__device__ __forceinline__ void mma16816(float* d, const uint32_t* a, uint32_t b0, uint32_t b1) {
    asm volatile("mma.sync.aligned.m16n8k16.row.col.f32.bf16.bf16.f32 "
        "{%0,%1,%2,%3}, {%4,%5,%6,%7}, {%8,%9}, {%0,%1,%2,%3};"
        : "+f"(d[0]), "+f"(d[1]), "+f"(d[2]), "+f"(d[3])
        : "r"(a[0]), "r"(a[1]), "r"(a[2]), "r"(a[3]), "r"(b0), "r"(b1));
}

// elu + bf16 hi/lo split of a packed pair
__device__ __forceinline__ void elusplit(float z0, float z1, uint32_t& hi, uint32_t& lo) {
    float c0 = (z0 > 0.f) ? z0 : (__expf(z0) - 1.f);
    float c1 = (z1 > 0.f) ? z1 : (__expf(z1) - 1.f);
    __nv_bfloat162 bh = __floats2bfloat162_rn(c0, c1);
    uint32_t u = *reinterpret_cast<uint32_t*>(&bh);
    float f0 = __uint_as_float(u << 16);
    float f1 = __uint_as_float(u & 0xffff0000u);
    __nv_bfloat162 bl = __floats2bfloat162_rn(c0 - f0, c1 - f1);
    hi = u;
    lo = *reinterpret_cast<uint32_t*>(&bl);
}

__device__ __forceinline__ float wcol(const float* Wpi, const float* Wsig,
                                      const float* Wmu, int k, int n) {
    if (n < 10)  return Wpi [k * 10 + n];
    if (n < 20)  return Wsig[k * 10 + (n - 10)];
    if (n < 30)  return Wmu [k * 10 + (n - 20)];
    return 0.f;
}

// ================= prep kernel =================
// blocks 0..143 gemm1, 144..271 bond, 272..335 atom, 336 B-frag build
__global__ void __launch_bounds__(256)
prep_kernel(const float* __restrict__ hlx, const float* __restrict__ htx,
            const void*  __restrict__ edge,
            const float* __restrict__ W1,  const float* __restrict__ b1,
            const float* __restrict__ gamma, const float* __restrict__ beta,
            const float* __restrict__ rmean, const float* __restrict__ rvar,
            const float* __restrict__ Wat, const float* __restrict__ bat,
            const float* __restrict__ Wbd, const float* __restrict__ bbd,
            const float* __restrict__ Wpi, const float* __restrict__ Wsig,
            const float* __restrict__ Wmu,
            float* __restrict__ out)
{
    __shared__ __align__(16) char s_buf[20800];
    const int tid = threadIdx.x;

    if (blockIdx.x < 144) {
        float (*sX)[33]   = reinterpret_cast<float(*)[33]>(s_buf);
        float (*sWt)[128] = reinterpret_cast<float(*)[128]>(s_buf + 32*33*4);

        const int row0 = blockIdx.x * 32;
        const bool isL = (row0 < 512);
        const float* X   = isL ? hlx : htx;
        const int    xr0 = isL ? row0 : row0 - 512;
        const float* Wh  = W1 + (isL ? 0 : 128 * 128);
        const int tx = tid & 15, ty = tid >> 4;

        float acc[2][8];
#pragma unroll
        for (int i = 0; i < 2; i++)
#pragma unroll
            for (int j = 0; j < 8; j++) acc[i][j] = 0.f;

        for (int k0 = 0; k0 < 128; k0 += 32) {
            __syncthreads();
            {
                int idx = tid * 4;
                int r = idx >> 5, c = idx & 31;
                float4 v = *reinterpret_cast<const float4*>(X + (xr0 + r) * 128 + k0 + c);
                sX[r][c] = v.x; sX[r][c+1] = v.y; sX[r][c+2] = v.z; sX[r][c+3] = v.w;
            }
#pragma unroll
            for (int j = 0; j < 16; j++) {
                int idx = tid + 256 * j;
                int r = idx >> 7, c = idx & 127;
                sWt[r][c] = Wh[(k0 + r) * 128 + c];
            }
            __syncthreads();
#pragma unroll
            for (int ck = 0; ck < 32; ++ck) {
                float x0 = sX[ty*2][ck], x1 = sX[ty*2+1][ck];
#pragma unroll
                for (int j = 0; j < 8; j++) {
                    float w = sWt[ck][tx + 16*j];
                    acc[0][j] += x0 * w;
                    acc[1][j] += x1 * w;
                }
            }
        }

        if (isL) {
#pragma unroll
            for (int j = 0; j < 8; j++) {
                int h = tx + 16*j;
                float s = gamma[h] * rsqrtf(rvar[h] + BN_EPS);
#pragma unroll
                for (int i = 0; i < 2; i++)
                    g_ZL[(row0 + ty*2 + i) * 128 + h] = acc[i][j] * s;
            }
        } else {
            float* sT = reinterpret_cast<float*>(s_buf);   // [32][129]
            __syncthreads();
#pragma unroll
            for (int j = 0; j < 8; j++) {
                int h = tx + 16*j;
                float s   = gamma[h] * rsqrtf(rvar[h] + BN_EPS);
                float off = (b1[h] - rmean[h]) * s + beta[h];
#pragma unroll
                for (int i = 0; i < 2; i++)
                    sT[(ty*2 + i) * 129 + h] = acc[i][j] * s + off;
            }
            __syncthreads();
            const int n0 = row0 - 512;
#pragma unroll
            for (int it = 0; it < 16; it++) {
                int idx = tid + it * 256;
                int h = idx >> 5, rr = idx & 31;
                g_ZTt[h * 4096 + n0 + rr] = sT[rr * 129 + h];
            }
        }
    } else if (blockIdx.x < 272) {
        int* s_is64 = reinterpret_cast<int*>(s_buf);
        if (tid == 0) *s_is64 = 1;
        __syncthreads();
        const int* p32 = reinterpret_cast<const int*>(edge);
        if (p32[2*tid + 1] != 0) *s_is64 = 0;
        __syncthreads();
        const int is64 = *s_is64;

        const int wid = tid >> 5, lane = tid & 31;
        const int e = (blockIdx.x - 144) * 8 + wid;
        int src, dst;
        if (is64) {
            const long long* p = reinterpret_cast<const long long*>(edge);
            src = (int)p[e]; dst = (int)p[EE + e];
        } else {
            src = p32[e]; dst = p32[EE + e];
        }
        float4 xs = *reinterpret_cast<const float4*>(hlx + src * 128 + lane * 4);
        float4 xd = *reinterpret_cast<const float4*>(hlx + dst * 128 + lane * 4);
        float acc[6];
#pragma unroll
        for (int j = 0; j < 6; j++) acc[j] = 0.f;
        const float* xsv = reinterpret_cast<const float*>(&xs);
        const float* xdv = reinterpret_cast<const float*>(&xd);
#pragma unroll
        for (int i = 0; i < 4; i++) {
            int c = lane * 4 + i;
#pragma unroll
            for (int j = 0; j < 6; j++) {
                acc[j] += xsv[i] * __ldg(Wbd + c * 6 + j);
                acc[j] += xdv[i] * __ldg(Wbd + (128 + c) * 6 + j);
            }
        }
#pragma unroll
        for (int off = 16; off > 0; off >>= 1)
#pragma unroll
            for (int j = 0; j < 6; j++)
                acc[j] += __shfl_down_sync(0xffffffffu, acc[j], off);
        if (lane == 0)
#pragma unroll
            for (int j = 0; j < 6; j++)
                out[BOND_OFF + e * 6 + j] = acc[j] + bbd[j];
    } else if (blockIdx.x < 336) {
        float* sWat = reinterpret_cast<float*>(s_buf);      // [28][129]
        float* sX   = sWat + 28 * 129;                      // [8][128]
        const int row0 = (blockIdx.x - 272) * 8;

        for (int idx = tid; idx < 128 * 28; idx += 256) {
            int c = idx / 28, k = idx - c * 28;
            sWat[k * 129 + c] = Wat[idx];
        }
        for (int idx = tid; idx < 8 * 128; idx += 256)
            sX[idx] = hlx[row0 * 128 + idx];
        __syncthreads();

        const int r = tid >> 5, k = tid & 31;
        if (k < 28) {
            float acc = bat[k];
            const float* xr = sX + r * 128;
            const float* wr = sWat + k * 129;
#pragma unroll 8
            for (int c = 0; c < 128; c++) acc += xr[c] * wr[c];
            out[ATOM_OFF + (row0 + r) * 28 + k] = acc;
        }
    } else {
        // ---------- B-frag build: [half][ks][ns][lane] -> {bh0,bh1,bl0,bl1} ----------
#pragma unroll
        for (int i = 0; i < 4; i++) {
            int e = tid + 256 * i;              // 0..1023
            int lane = e & 31;
            int ns = (e >> 5) & 3;
            int ks = (e >> 7) & 3;
            int half = (e >> 9) & 1;
            int g = lane >> 2, tg = lane & 3;
            int n = ns * 8 + g;
            int kb = half * 64 + ks * 16 + tg * 2;

            float w0 = wcol(Wpi, Wsig, Wmu, kb,     n);
            float w1 = wcol(Wpi, Wsig, Wmu, kb + 1, n);
            float w2 = wcol(Wpi, Wsig, Wmu, kb + 8, n);
            float w3 = wcol(Wpi, Wsig, Wmu, kb + 9, n);

            __nv_bfloat162 h0 = __floats2bfloat162_rn(w0, w1);
            __nv_bfloat162 h1 = __floats2bfloat162_rn(w2, w3);
            uint32_t u0 = *reinterpret_cast<uint32_t*>(&h0);
            uint32_t u1 = *reinterpret_cast<uint32_t*>(&h1);
            __nv_bfloat162 l0 = __floats2bfloat162_rn(
                w0 - __uint_as_float(u0 << 16), w1 - __uint_as_float(u0 & 0xffff0000u));
            __nv_bfloat162 l1 = __floats2bfloat162_rn(
                w2 - __uint_as_float(u1 << 16), w3 - __uint_as_float(u1 & 0xffff0000u));
            g_Bfrag[e] = make_uint4(u0, u1,
                                    *reinterpret_cast<uint32_t*>(&l0),
                                    *reinterpret_cast<uint32_t*>(&l1));
        }
    }
}

// ================= pair kernel: HMMA, A fragments built in registers =================
// grid 2048 = (b*64+l) x 4 t-tiles of 128. 128 threads; warp w owns rows w*32..+31.
__global__ void __launch_bounds__(128, 6)
pair_hmma_kernel(const float* __restrict__ hlpos, const float* __restrict__ htpos,
                 const float* __restrict__ bpi, const float* __restrict__ bsig,
                 const float* __restrict__ bmu, float* __restrict__ out)
{
    extern __shared__ __align__(16) char sm[];
    const int tid  = threadIdx.x;
    const int w    = tid >> 5;
    const int lane = tid & 31;
    const int g    = lane >> 2, tg = lane & 3;

    const int bid  = blockIdx.x;
    const int bid2 = bid >> 2;          // b*64 + l
    const int tile = bid & 3;
    const int b    = bid2 >> 6;
    const int n0   = b * 512 + tile * 128;

    float* sZL   = reinterpret_cast<float*>(sm + SZL_OFF);
    float* sBias = reinterpret_cast<float*>(sm + SBIAS_OFF);

    // ---- block init ----
#pragma unroll
    for (int i = 0; i < 8; i++)
        reinterpret_cast<uint4*>(sm + SBF)[tid + 128 * i] = g_Bfrag[tid + 128 * i];
    sZL[tid] = g_ZL[bid2 * 128 + tid];
    if (tid < 32) {
        float bv = 0.f;
        if (tid < 10)      bv = bpi [tid];
        else if (tid < 20) bv = bsig[tid - 10];
        else if (tid < 30) bv = bmu [tid - 20];
        sBias[tid] = bv;
    }
    __syncthreads();

    float d[2][4][4];
#pragma unroll
    for (int ms = 0; ms < 2; ms++)
#pragma unroll
        for (int ns = 0; ns < 4; ns++)
#pragma unroll
            for (int i = 0; i < 4; i++) d[ms][ns][i] = 0.f;

    const int colbase = n0 + w * 32 + g;

#pragma unroll
    for (int half = 0; half < 2; half++) {
#pragma unroll
        for (int ks = 0; ks < 4; ks++) {
            const int hb = half * 64 + ks * 16 + tg * 2;
            const float zl0 = sZL[hb],     zl1 = sZL[hb + 1];
            const float zl2 = sZL[hb + 8], zl3 = sZL[hb + 9];

            uint32_t ahi[2][4], alo[2][4];
#pragma unroll
            for (int ms = 0; ms < 2; ms++) {
                const float* zp = g_ZTt + hb * 4096 + colbase + ms * 16;
                float z00 = zp[0],         z01 = zp[8];          // h=hb     rows g,g+8
                float z10 = zp[4096],      z11 = zp[4096 + 8];   // h=hb+1
                float z20 = zp[8 * 4096],  z21 = zp[8 * 4096 + 8];  // h=hb+8
                float z30 = zp[9 * 4096],  z31 = zp[9 * 4096 + 8];  // h=hb+9
                elusplit(z00 + zl0, z10 + zl1, ahi[ms][0], alo[ms][0]);  // row g,   k lo-pair
                elusplit(z01 + zl0, z11 + zl1, ahi[ms][1], alo[ms][1]);  // row g+8, k lo-pair
                elusplit(z20 + zl2, z30 + zl3, ahi[ms][2], alo[ms][2]);  // row g,   k hi-pair
                elusplit(z21 + zl2, z31 + zl3, ahi[ms][3], alo[ms][3]);  // row g+8, k hi-pair
            }
#pragma unroll
            for (int ns = 0; ns < 4; ns++) {
                uint4 bf = *reinterpret_cast<const uint4*>(
                    sm + SBF + ((((half * 4 + ks) * 4 + ns) * 32 + lane) << 4));
#pragma unroll
                for (int ms = 0; ms < 2; ms++) {
                    mma16816(d[ms][ns], ahi[ms], bf.x, bf.y);
                    mma16816(d[ms][ns], alo[ms], bf.x, bf.y);
                    mma16816(d[ms][ns], ahi[ms], bf.z, bf.w);
                }
            }
        }
    }

    // ---- D -> warp's smem slice (row-major, stride 132B, scalar 4B stores) ----
    char* sd = sm + SD_OFF + w * SD_WARP;
#pragma unroll
    for (int ms = 0; ms < 2; ms++)
#pragma unroll
        for (int ns = 0; ns < 4; ns++) {
            int r0 = ms * 16 + g;
            int cb = (ns * 8 + tg * 2) * 4;
            *reinterpret_cast<float*>(sd + r0 * 132 + cb)           = d[ms][ns][0];
            *reinterpret_cast<float*>(sd + r0 * 132 + cb + 4)       = d[ms][ns][1];
            *reinterpret_cast<float*>(sd + (r0 + 8) * 132 + cb)     = d[ms][ns][2];
            *reinterpret_cast<float*>(sd + (r0 + 8) * 132 + cb + 4) = d[ms][ns][3];
        }
    __syncwarp();

    // ---- epilogue: thread owns pair row = tid ----
    {
        const int t = tile * 128 + tid;
        const int p = bid2 * 512 + t;
        const char* drow = sd + lane * 132;

        float v[30];
#pragma unroll
        for (int k = 0; k < 30; k++)
            v[k] = *reinterpret_cast<const float*>(drow + k * 4) + sBias[k];

        float m = v[0];
#pragma unroll
        for (int k = 1; k < 10; k++) m = fmaxf(m, v[k]);
        float e[10], s = 0.f;
#pragma unroll
        for (int k = 0; k < 10; k++) { e[k] = __expf(v[k] - m); s += e[k]; }
        float inv = __fdividef(1.f, s);
#pragma unroll
        for (int k = 0; k < 10; k++) out[PI_OFF + p * 10 + k] = e[k] * inv;

#pragma unroll
        for (int k = 0; k < 10; k++) {
            float x = v[10 + k];
            float r = (x > 0.f) ? x : (__expf(x) - 1.f);
            out[SIG_OFF + p * 10 + k] = r + 1.1f;
        }
#pragma unroll
        for (int k = 0; k < 10; k++) {
            float x = v[20 + k];
            float r = (x > 0.f) ? x : (__expf(x) - 1.f);
            out[MU_OFF + p * 10 + k] = r + 1.0f;
        }

        const float plx = hlpos[bid2 * 3 + 0];
        const float ply = hlpos[bid2 * 3 + 1];
        const float plz = hlpos[bid2 * 3 + 2];
        const float* pt = htpos + (b * 512 + t) * 3;
        float d2 = -2.f * (plx * pt[0] + ply * pt[1] + plz * pt[2])
                 + (pt[0]*pt[0] + pt[1]*pt[1] + pt[2]*pt[2])
                 + (plx*plx + ply*ply + plz*plz);
        out[DIST_OFF + p] = sqrtf(d2);
        out[CB_OFF + p] = (float)b;
    }
}

// ---------------- launch ----------------
extern "C" void kernel_launch(void* const* d_in, const int* in_sizes, int n_in,
                              void* d_out, int out_size)
{
    const float* hlx   = (const float*)d_in[0];
    const float* htx   = (const float*)d_in[1];
    const float* hlpos = (const float*)d_in[2];
    const float* htpos = (const float*)d_in[3];
    const void*  edge  = d_in[4];
    const float* W1    = (const float*)d_in[5];
    const float* b1    = (const float*)d_in[6];
    const float* gamma = (const float*)d_in[7];
    const float* beta  = (const float*)d_in[8];
    const float* rmean = (const float*)d_in[9];
    const float* rvar  = (const float*)d_in[10];
    const float* Wpi   = (const float*)d_in[11];
    const float* bpi   = (const float*)d_in[12];
    const float* Wsig  = (const float*)d_in[13];
    const float* bsig  = (const float*)d_in[14];
    const float* Wmu   = (const float*)d_in[15];
    const float* bmu   = (const float*)d_in[16];
    const float* Wat   = (const float*)d_in[17];
    const float* bat   = (const float*)d_in[18];
    const float* Wbd   = (const float*)d_in[19];
    const float* bbd   = (const float*)d_in[20];
    float* out = (float*)d_out;

    cudaFuncSetAttribute(pair_hmma_kernel, cudaFuncAttributeMaxDynamicSharedMemorySize, SMEM_TOTAL);

    prep_kernel<<<337, 256>>>(hlx, htx, edge, W1, b1, gamma, beta, rmean, rvar,
                              Wat, bat, Wbd, bbd, Wpi, Wsig, Wmu, out);
    pair_hmma_kernel<<<2048, 128, SMEM_TOTAL>>>(hlpos, htpos, bpi, bsig, bmu, out);
}

// round 16
// speedup vs baseline: 1.7776x; 1.0034x over previous
#include <cuda_runtime.h>
#include <cuda_bf16.h>
#include <cstdint>

// ---------------- problem constants ----------------
#define BB 8
#define NL 64
#define NT 512
#define CF 128
#define HH 128
#define KK 10
#define EE 1024
#define BN_EPS 1e-4f

#define PI_OFF   0
#define SIG_OFF  2621440
#define MU_OFF   5242880
#define DIST_OFF 7864320
#define ATOM_OFF 8126464
#define BOND_OFF 8140800
#define CB_OFF   8146944

// ---------------- scratch ----------------
__device__ float g_ZL[512 * 128];        // (b*NL+l, h) : zl*s
__device__ float g_ZTt[128 * 4096];      // [h][b*512+t]: zt*s + (b1-mu)*s + beta  (transposed)
__device__ uint4 g_Bfrag[1024];          // [half][ks][ns][lane] = {bh0, bh1, bl0, bl1}

// ---------------- shared layout of pair kernel (dynamic) ----------------
// B frags + zL live during the main loop; D writeback OVERLAYS them afterwards
// (guarded by __syncthreads()).
#define SBF        0                      // B fragments, 16384 B
#define SZL_OFF    16384                  // 128 f32
#define SBIAS_OFF  16896                  // 32 f32 (never overlaid)
#define SMEM_TOTAL 17024
#define SD_OFF     0                      // D writeback: 4 warps x 4224 B = 16896
#define SD_WARP    4224

__device__ __forceinline__ void mma16816(float* d, const uint32_t* a, uint32_t b0, uint32_t b1) {
    asm volatile("mma.sync.aligned.m16n8k16.row.col.f32.bf16.bf16.f32 "
        "{%0,%1,%2,%3}, {%4,%5,%6,%7}, {%8,%9}, {%0,%1,%2,%3};"
        : "+f"(d[0]), "+f"(d[1]), "+f"(d[2]), "+f"(d[3])
        : "r"(a[0]), "r"(a[1]), "r"(a[2]), "r"(a[3]), "r"(b0), "r"(b1));
}

// elu + bf16 hi/lo split of a packed pair
__device__ __forceinline__ void elusplit(float z0, float z1, uint32_t& hi, uint32_t& lo) {
    float c0 = (z0 > 0.f) ? z0 : (__expf(z0) - 1.f);
    float c1 = (z1 > 0.f) ? z1 : (__expf(z1) - 1.f);
    __nv_bfloat162 bh = __floats2bfloat162_rn(c0, c1);
    uint32_t u = *reinterpret_cast<uint32_t*>(&bh);
    float f0 = __uint_as_float(u << 16);
    float f1 = __uint_as_float(u & 0xffff0000u);
    __nv_bfloat162 bl = __floats2bfloat162_rn(c0 - f0, c1 - f1);
    hi = u;
    lo = *reinterpret_cast<uint32_t*>(&bl);
}

__device__ __forceinline__ float wcol(const float* Wpi, const float* Wsig,
                                      const float* Wmu, int k, int n) {
    if (n < 10)  return Wpi [k * 10 + n];
    if (n < 20)  return Wsig[k * 10 + (n - 10)];
    if (n < 30)  return Wmu [k * 10 + (n - 20)];
    return 0.f;
}

// ================= prep kernel =================
// blocks 0..143 gemm1, 144..271 bond, 272..335 atom, 336 B-frag build
__global__ void __launch_bounds__(256)
prep_kernel(const float* __restrict__ hlx, const float* __restrict__ htx,
            const void*  __restrict__ edge,
            const float* __restrict__ W1,  const float* __restrict__ b1,
            const float* __restrict__ gamma, const float* __restrict__ beta,
            const float* __restrict__ rmean, const float* __restrict__ rvar,
            const float* __restrict__ Wat, const float* __restrict__ bat,
            const float* __restrict__ Wbd, const float* __restrict__ bbd,
            const float* __restrict__ Wpi, const float* __restrict__ Wsig,
            const float* __restrict__ Wmu,
            float* __restrict__ out)
{
    __shared__ __align__(16) char s_buf[20800];
    const int tid = threadIdx.x;

    if (blockIdx.x < 144) {
        float (*sX)[33]   = reinterpret_cast<float(*)[33]>(s_buf);
        float (*sWt)[128] = reinterpret_cast<float(*)[128]>(s_buf + 32*33*4);

        const int row0 = blockIdx.x * 32;
        const bool isL = (row0 < 512);
        const float* X   = isL ? hlx : htx;
        const int    xr0 = isL ? row0 : row0 - 512;
        const float* Wh  = W1 + (isL ? 0 : 128 * 128);
        const int tx = tid & 15, ty = tid >> 4;

        float acc[2][8];
#pragma unroll
        for (int i = 0; i < 2; i++)
#pragma unroll
            for (int j = 0; j < 8; j++) acc[i][j] = 0.f;

        for (int k0 = 0; k0 < 128; k0 += 32) {
            __syncthreads();
            {
                int idx = tid * 4;
                int r = idx >> 5, c = idx & 31;
                float4 v = *reinterpret_cast<const float4*>(X + (xr0 + r) * 128 + k0 + c);
                sX[r][c] = v.x; sX[r][c+1] = v.y; sX[r][c+2] = v.z; sX[r][c+3] = v.w;
            }
#pragma unroll
            for (int j = 0; j < 16; j++) {
                int idx = tid + 256 * j;
                int r = idx >> 7, c = idx & 127;
                sWt[r][c] = Wh[(k0 + r) * 128 + c];
            }
            __syncthreads();
#pragma unroll
            for (int ck = 0; ck < 32; ++ck) {
                float x0 = sX[ty*2][ck], x1 = sX[ty*2+1][ck];
#pragma unroll
                for (int j = 0; j < 8; j++) {
                    float w = sWt[ck][tx + 16*j];
                    acc[0][j] += x0 * w;
                    acc[1][j] += x1 * w;
                }
            }
        }

        if (isL) {
#pragma unroll
            for (int j = 0; j < 8; j++) {
                int h = tx + 16*j;
                float s = gamma[h] * rsqrtf(rvar[h] + BN_EPS);
#pragma unroll
                for (int i = 0; i < 2; i++)
                    g_ZL[(row0 + ty*2 + i) * 128 + h] = acc[i][j] * s;
            }
        } else {
            float* sT = reinterpret_cast<float*>(s_buf);   // [32][129]
            __syncthreads();
#pragma unroll
            for (int j = 0; j < 8; j++) {
                int h = tx + 16*j;
                float s   = gamma[h] * rsqrtf(rvar[h] + BN_EPS);
                float off = (b1[h] - rmean[h]) * s + beta[h];
#pragma unroll
                for (int i = 0; i < 2; i++)
                    sT[(ty*2 + i) * 129 + h] = acc[i][j] * s + off;
            }
            __syncthreads();
            const int n0 = row0 - 512;
#pragma unroll
            for (int it = 0; it < 16; it++) {
                int idx = tid + it * 256;
                int h = idx >> 5, rr = idx & 31;
                g_ZTt[h * 4096 + n0 + rr] = sT[rr * 129 + h];
            }
        }
    } else if (blockIdx.x < 272) {
        int* s_is64 = reinterpret_cast<int*>(s_buf);
        if (tid == 0) *s_is64 = 1;
        __syncthreads();
        const int* p32 = reinterpret_cast<const int*>(edge);
        if (p32[2*tid + 1] != 0) *s_is64 = 0;
        __syncthreads();
        const int is64 = *s_is64;

        const int wid = tid >> 5, lane = tid & 31;
        const int e = (blockIdx.x - 144) * 8 + wid;
        int src, dst;
        if (is64) {
            const long long* p = reinterpret_cast<const long long*>(edge);
            src = (int)p[e]; dst = (int)p[EE + e];
        } else {
            src = p32[e]; dst = p32[EE + e];
        }
        float4 xs = *reinterpret_cast<const float4*>(hlx + src * 128 + lane * 4);
        float4 xd = *reinterpret_cast<const float4*>(hlx + dst * 128 + lane * 4);
        float acc[6];
#pragma unroll
        for (int j = 0; j < 6; j++) acc[j] = 0.f;
        const float* xsv = reinterpret_cast<const float*>(&xs);
        const float* xdv = reinterpret_cast<const float*>(&xd);
#pragma unroll
        for (int i = 0; i < 4; i++) {
            int c = lane * 4 + i;
#pragma unroll
            for (int j = 0; j < 6; j++) {
                acc[j] += xsv[i] * __ldg(Wbd + c * 6 + j);
                acc[j] += xdv[i] * __ldg(Wbd + (128 + c) * 6 + j);
            }
        }
#pragma unroll
        for (int off = 16; off > 0; off >>= 1)
#pragma unroll
            for (int j = 0; j < 6; j++)
                acc[j] += __shfl_down_sync(0xffffffffu, acc[j], off);
        if (lane == 0)
#pragma unroll
            for (int j = 0; j < 6; j++)
                out[BOND_OFF + e * 6 + j] = acc[j] + bbd[j];
    } else if (blockIdx.x < 336) {
        float* sWat = reinterpret_cast<float*>(s_buf);      // [28][129]
        float* sX   = sWat + 28 * 129;                      // [8][128]
        const int row0 = (blockIdx.x - 272) * 8;

        for (int idx = tid; idx < 128 * 28; idx += 256) {
            int c = idx / 28, k = idx - c * 28;
            sWat[k * 129 + c] = Wat[idx];
        }
        for (int idx = tid; idx < 8 * 128; idx += 256)
            sX[idx] = hlx[row0 * 128 + idx];
        __syncthreads();

        const int r = tid >> 5, k = tid & 31;
        if (k < 28) {
            float acc = bat[k];
            const float* xr = sX + r * 128;
            const float* wr = sWat + k * 129;
#pragma unroll 8
            for (int c = 0; c < 128; c++) acc += xr[c] * wr[c];
            out[ATOM_OFF + (row0 + r) * 28 + k] = acc;
        }
    } else {
        // ---------- B-frag build: [half][ks][ns][lane] -> {bh0,bh1,bl0,bl1} ----------
#pragma unroll
        for (int i = 0; i < 4; i++) {
            int e = tid + 256 * i;              // 0..1023
            int lane = e & 31;
            int ns = (e >> 5) & 3;
            int ks = (e >> 7) & 3;
            int half = (e >> 9) & 1;
            int g = lane >> 2, tg = lane & 3;
            int n = ns * 8 + g;
            int kb = half * 64 + ks * 16 + tg * 2;

            float w0 = wcol(Wpi, Wsig, Wmu, kb,     n);
            float w1 = wcol(Wpi, Wsig, Wmu, kb + 1, n);
            float w2 = wcol(Wpi, Wsig, Wmu, kb + 8, n);
            float w3 = wcol(Wpi, Wsig, Wmu, kb + 9, n);

            __nv_bfloat162 h0 = __floats2bfloat162_rn(w0, w1);
            __nv_bfloat162 h1 = __floats2bfloat162_rn(w2, w3);
            uint32_t u0 = *reinterpret_cast<uint32_t*>(&h0);
            uint32_t u1 = *reinterpret_cast<uint32_t*>(&h1);
            __nv_bfloat162 l0 = __floats2bfloat162_rn(
                w0 - __uint_as_float(u0 << 16), w1 - __uint_as_float(u0 & 0xffff0000u));
            __nv_bfloat162 l1 = __floats2bfloat162_rn(
                w2 - __uint_as_float(u1 << 16), w3 - __uint_as_float(u1 & 0xffff0000u));
            g_Bfrag[e] = make_uint4(u0, u1,
                                    *reinterpret_cast<uint32_t*>(&l0),
                                    *reinterpret_cast<uint32_t*>(&l1));
        }
    }
}

// ================= pair kernel: HMMA, reg A-fragments + cross-step prefetch =================
// grid 2048 = (b*64+l) x 4 t-tiles of 128. 128 threads; warp w owns rows w*32..+31.
__global__ void __launch_bounds__(128, 5)
pair_hmma_kernel(const float* __restrict__ hlpos, const float* __restrict__ htpos,
                 const float* __restrict__ bpi, const float* __restrict__ bsig,
                 const float* __restrict__ bmu, float* __restrict__ out)
{
    extern __shared__ __align__(16) char sm[];
    const int tid  = threadIdx.x;
    const int w    = tid >> 5;
    const int lane = tid & 31;
    const int g    = lane >> 2, tg = lane & 3;

    const int bid  = blockIdx.x;
    const int bid2 = bid >> 2;          // b*64 + l
    const int tile = bid & 3;
    const int b    = bid2 >> 6;
    const int n0   = b * 512 + tile * 128;

    float* sZL   = reinterpret_cast<float*>(sm + SZL_OFF);
    float* sBias = reinterpret_cast<float*>(sm + SBIAS_OFF);

    // ---- block init ----
#pragma unroll
    for (int i = 0; i < 8; i++)
        reinterpret_cast<uint4*>(sm + SBF)[tid + 128 * i] = g_Bfrag[tid + 128 * i];
    sZL[tid] = g_ZL[bid2 * 128 + tid];
    if (tid < 32) {
        float bv = 0.f;
        if (tid < 10)      bv = bpi [tid];
        else if (tid < 20) bv = bsig[tid - 10];
        else if (tid < 30) bv = bmu [tid - 20];
        sBias[tid] = bv;
    }
    __syncthreads();

    float d[2][4][4];
#pragma unroll
    for (int ms = 0; ms < 2; ms++)
#pragma unroll
        for (int ns = 0; ns < 4; ns++)
#pragma unroll
            for (int i = 0; i < 4; i++) d[ms][ns][i] = 0.f;

    const float* zbase = g_ZTt + n0 + w * 32 + g + (tg * 2) * 4096;

    // load the 16 z-values of one step (step = half*4+ks): dst[ms*8 + {0..7}]
    auto LOADZ = [&](float* dst, int step) {
        const float* zp = zbase + (step * 16) * 4096;
#pragma unroll
        for (int ms = 0; ms < 2; ms++) {
            const float* q = zp + ms * 16;
            dst[ms*8 + 0] = q[0];            dst[ms*8 + 1] = q[8];
            dst[ms*8 + 2] = q[4096];         dst[ms*8 + 3] = q[4096 + 8];
            dst[ms*8 + 4] = q[8 * 4096];     dst[ms*8 + 5] = q[8 * 4096 + 8];
            dst[ms*8 + 6] = q[9 * 4096];     dst[ms*8 + 7] = q[9 * 4096 + 8];
        }
    };

    float zbuf[2][16];
    LOADZ(zbuf[0], 0);

#pragma unroll
    for (int step = 0; step < 8; step++) {
        // prefetch next step's z FIRST (hidden under elusplit + MMA below)
        if (step < 7) LOADZ(zbuf[(step + 1) & 1], step + 1);

        const float* cur = zbuf[step & 1];
        const int hb = step * 16 + tg * 2;
        const float zl0 = sZL[hb],     zl1 = sZL[hb + 1];
        const float zl2 = sZL[hb + 8], zl3 = sZL[hb + 9];

        uint32_t ahi[2][4], alo[2][4];
#pragma unroll
        for (int ms = 0; ms < 2; ms++) {
            elusplit(cur[ms*8 + 0] + zl0, cur[ms*8 + 2] + zl1, ahi[ms][0], alo[ms][0]);
            elusplit(cur[ms*8 + 1] + zl0, cur[ms*8 + 3] + zl1, ahi[ms][1], alo[ms][1]);
            elusplit(cur[ms*8 + 4] + zl2, cur[ms*8 + 6] + zl3, ahi[ms][2], alo[ms][2]);
            elusplit(cur[ms*8 + 5] + zl2, cur[ms*8 + 7] + zl3, ahi[ms][3], alo[ms][3]);
        }
#pragma unroll
        for (int ns = 0; ns < 4; ns++) {
            uint4 bf = *reinterpret_cast<const uint4*>(
                sm + SBF + (((step * 4 + ns) * 32 + lane) << 4));
#pragma unroll
            for (int ms = 0; ms < 2; ms++) {
                mma16816(d[ms][ns], ahi[ms], bf.x, bf.y);
                mma16816(d[ms][ns], alo[ms], bf.x, bf.y);
                mma16816(d[ms][ns], ahi[ms], bf.z, bf.w);
            }
        }
    }

    // ---- all warps done with B frags / zL: overlay D region on top of them ----
    __syncthreads();

    char* sd = sm + SD_OFF + w * SD_WARP;
#pragma unroll
    for (int ms = 0; ms < 2; ms++)
#pragma unroll
        for (int ns = 0; ns < 4; ns++) {
            int r0 = ms * 16 + g;
            int cb = (ns * 8 + tg * 2) * 4;
            *reinterpret_cast<float*>(sd + r0 * 132 + cb)           = d[ms][ns][0];
            *reinterpret_cast<float*>(sd + r0 * 132 + cb + 4)       = d[ms][ns][1];
            *reinterpret_cast<float*>(sd + (r0 + 8) * 132 + cb)     = d[ms][ns][2];
            *reinterpret_cast<float*>(sd + (r0 + 8) * 132 + cb + 4) = d[ms][ns][3];
        }
    __syncwarp();

    // ---- epilogue: thread owns pair row = tid ----
    {
        const int t = tile * 128 + tid;
        const int p = bid2 * 512 + t;
        const char* drow = sd + lane * 132;

        float v[30];
#pragma unroll
        for (int k = 0; k < 30; k++)
            v[k] = *reinterpret_cast<const float*>(drow + k * 4) + sBias[k];

        float m = v[0];
#pragma unroll
        for (int k = 1; k < 10; k++) m = fmaxf(m, v[k]);
        float e[10], s = 0.f;
#pragma unroll
        for (int k = 0; k < 10; k++) { e[k] = __expf(v[k] - m); s += e[k]; }
        float inv = __fdividef(1.f, s);
#pragma unroll
        for (int k = 0; k < 10; k++) out[PI_OFF + p * 10 + k] = e[k] * inv;

#pragma unroll
        for (int k = 0; k < 10; k++) {
            float x = v[10 + k];
            float r = (x > 0.f) ? x : (__expf(x) - 1.f);
            out[SIG_OFF + p * 10 + k] = r + 1.1f;
        }
#pragma unroll
        for (int k = 0; k < 10; k++) {
            float x = v[20 + k];
            float r = (x > 0.f) ? x : (__expf(x) - 1.f);
            out[MU_OFF + p * 10 + k] = r + 1.0f;
        }

        const float plx = hlpos[bid2 * 3 + 0];
        const float ply = hlpos[bid2 * 3 + 1];
        const float plz = hlpos[bid2 * 3 + 2];
        const float* pt = htpos + (b * 512 + t) * 3;
        float d2 = -2.f * (plx * pt[0] + ply * pt[1] + plz * pt[2])
                 + (pt[0]*pt[0] + pt[1]*pt[1] + pt[2]*pt[2])
                 + (plx*plx + ply*ply + plz*plz);
        out[DIST_OFF + p] = sqrtf(d2);
        out[CB_OFF + p] = (float)b;
    }
}

// ---------------- launch ----------------
extern "C" void kernel_launch(void* const* d_in, const int* in_sizes, int n_in,
                              void* d_out, int out_size)
{
    const float* hlx   = (const float*)d_in[0];
    const float* htx   = (const float*)d_in[1];
    const float* hlpos = (const float*)d_in[2];
    const float* htpos = (const float*)d_in[3];
    const void*  edge  = d_in[4];
    const float* W1    = (const float*)d_in[5];
    const float* b1    = (const float*)d_in[6];
    const float* gamma = (const float*)d_in[7];
    const float* beta  = (const float*)d_in[8];
    const float* rmean = (const float*)d_in[9];
    const float* rvar  = (const float*)d_in[10];
    const float* Wpi   = (const float*)d_in[11];
    const float* bpi   = (const float*)d_in[12];
    const float* Wsig  = (const float*)d_in[13];
    const float* bsig  = (const float*)d_in[14];
    const float* Wmu   = (const float*)d_in[15];
    const float* bmu   = (const float*)d_in[16];
    const float* Wat   = (const float*)d_in[17];
    const float* bat   = (const float*)d_in[18];
    const float* Wbd   = (const float*)d_in[19];
    const float* bbd   = (const float*)d_in[20];
    float* out = (float*)d_out;

    cudaFuncSetAttribute(pair_hmma_kernel, cudaFuncAttributeMaxDynamicSharedMemorySize, SMEM_TOTAL);

    prep_kernel<<<337, 256>>>(hlx, htx, edge, W1, b1, gamma, beta, rmean, rvar,
                              Wat, bat, Wbd, bbd, Wpi, Wsig, Wmu, out);
    pair_hmma_kernel<<<2048, 128, SMEM_TOTAL>>>(hlpos, htpos, bpi, bsig, bmu, out);
}

// round 17
// speedup vs baseline: 2.2030x; 1.2393x over previous
#include <cuda_runtime.h>
#include <cuda_bf16.h>
#include <cstdint>

// ---------------- problem constants ----------------
#define BB 8
#define NL 64
#define NT 512
#define CF 128
#define HH 128
#define KK 10
#define EE 1024
#define BN_EPS 1e-4f

#define PI_OFF   0
#define SIG_OFF  2621440
#define MU_OFF   5242880
#define DIST_OFF 7864320
#define ATOM_OFF 8126464
#define BOND_OFF 8140800
#define CB_OFF   8146944

// ---------------- scratch ----------------
__device__ float g_ZL[512 * 128];        // (b*NL+l, h) : zl*s
__device__ float g_ZTt[128 * 4096];      // [h][b*512+t]: zt*s + (b1-mu)*s + beta  (transposed)
__device__ uint4 g_Bfrag[1024];          // [half][ks][ns][lane] = {bh0, bh1, bl0, bl1}

// ---------------- shared layout of pair kernel (dynamic) ----------------
// Phase A (main loop): B frags [0,16384) + zL [16384,16896)
// Phase B (D shuffle): per-warp D slices [0,16896)          (after barrier)
// Phase C (out stage): 3840-float output buffer [0,15360)   (after barrier)
// sBias at [16896,17024) lives through all phases.
#define SBF        0
#define SZL_OFF    16384
#define SBIAS_OFF  16896
#define SMEM_TOTAL 17024
#define SD_OFF     0
#define SD_WARP    4224

__device__ __forceinline__ void mma16816(float* d, const uint32_t* a, uint32_t b0, uint32_t b1) {
    asm volatile("mma.sync.aligned.m16n8k16.row.col.f32.bf16.bf16.f32 "
        "{%0,%1,%2,%3}, {%4,%5,%6,%7}, {%8,%9}, {%0,%1,%2,%3};"
        : "+f"(d[0]), "+f"(d[1]), "+f"(d[2]), "+f"(d[3])
        : "r"(a[0]), "r"(a[1]), "r"(a[2]), "r"(a[3]), "r"(b0), "r"(b1));
}

// elu + bf16 hi/lo split of a packed pair
__device__ __forceinline__ void elusplit(float z0, float z1, uint32_t& hi, uint32_t& lo) {
    float c0 = (z0 > 0.f) ? z0 : (__expf(z0) - 1.f);
    float c1 = (z1 > 0.f) ? z1 : (__expf(z1) - 1.f);
    __nv_bfloat162 bh = __floats2bfloat162_rn(c0, c1);
    uint32_t u = *reinterpret_cast<uint32_t*>(&bh);
    float f0 = __uint_as_float(u << 16);
    float f1 = __uint_as_float(u & 0xffff0000u);
    __nv_bfloat162 bl = __floats2bfloat162_rn(c0 - f0, c1 - f1);
    hi = u;
    lo = *reinterpret_cast<uint32_t*>(&bl);
}

__device__ __forceinline__ float wcol(const float* Wpi, const float* Wsig,
                                      const float* Wmu, int k, int n) {
    if (n < 10)  return Wpi [k * 10 + n];
    if (n < 20)  return Wsig[k * 10 + (n - 10)];
    if (n < 30)  return Wmu [k * 10 + (n - 20)];
    return 0.f;
}

// ================= prep kernel =================
// blocks 0..143 gemm1, 144..271 bond, 272..335 atom, 336 B-frag build
__global__ void __launch_bounds__(256)
prep_kernel(const float* __restrict__ hlx, const float* __restrict__ htx,
            const void*  __restrict__ edge,
            const float* __restrict__ W1,  const float* __restrict__ b1,
            const float* __restrict__ gamma, const float* __restrict__ beta,
            const float* __restrict__ rmean, const float* __restrict__ rvar,
            const float* __restrict__ Wat, const float* __restrict__ bat,
            const float* __restrict__ Wbd, const float* __restrict__ bbd,
            const float* __restrict__ Wpi, const float* __restrict__ Wsig,
            const float* __restrict__ Wmu,
            float* __restrict__ out)
{
    __shared__ __align__(16) char s_buf[20800];
    const int tid = threadIdx.x;

    if (blockIdx.x < 144) {
        float (*sX)[33]   = reinterpret_cast<float(*)[33]>(s_buf);
        float (*sWt)[128] = reinterpret_cast<float(*)[128]>(s_buf + 32*33*4);

        const int row0 = blockIdx.x * 32;
        const bool isL = (row0 < 512);
        const float* X   = isL ? hlx : htx;
        const int    xr0 = isL ? row0 : row0 - 512;
        const float* Wh  = W1 + (isL ? 0 : 128 * 128);
        const int tx = tid & 15, ty = tid >> 4;

        float acc[2][8];
#pragma unroll
        for (int i = 0; i < 2; i++)
#pragma unroll
            for (int j = 0; j < 8; j++) acc[i][j] = 0.f;

        for (int k0 = 0; k0 < 128; k0 += 32) {
            __syncthreads();
            {
                int idx = tid * 4;
                int r = idx >> 5, c = idx & 31;
                float4 v = *reinterpret_cast<const float4*>(X + (xr0 + r) * 128 + k0 + c);
                sX[r][c] = v.x; sX[r][c+1] = v.y; sX[r][c+2] = v.z; sX[r][c+3] = v.w;
            }
#pragma unroll
            for (int j = 0; j < 16; j++) {
                int idx = tid + 256 * j;
                int r = idx >> 7, c = idx & 127;
                sWt[r][c] = Wh[(k0 + r) * 128 + c];
            }
            __syncthreads();
#pragma unroll
            for (int ck = 0; ck < 32; ++ck) {
                float x0 = sX[ty*2][ck], x1 = sX[ty*2+1][ck];
#pragma unroll
                for (int j = 0; j < 8; j++) {
                    float w = sWt[ck][tx + 16*j];
                    acc[0][j] += x0 * w;
                    acc[1][j] += x1 * w;
                }
            }
        }

        if (isL) {
#pragma unroll
            for (int j = 0; j < 8; j++) {
                int h = tx + 16*j;
                float s = gamma[h] * rsqrtf(rvar[h] + BN_EPS);
#pragma unroll
                for (int i = 0; i < 2; i++)
                    g_ZL[(row0 + ty*2 + i) * 128 + h] = acc[i][j] * s;
            }
        } else {
            float* sT = reinterpret_cast<float*>(s_buf);   // [32][129]
            __syncthreads();
#pragma unroll
            for (int j = 0; j < 8; j++) {
                int h = tx + 16*j;
                float s   = gamma[h] * rsqrtf(rvar[h] + BN_EPS);
                float off = (b1[h] - rmean[h]) * s + beta[h];
#pragma unroll
                for (int i = 0; i < 2; i++)
                    sT[(ty*2 + i) * 129 + h] = acc[i][j] * s + off;
            }
            __syncthreads();
            const int n0 = row0 - 512;
#pragma unroll
            for (int it = 0; it < 16; it++) {
                int idx = tid + it * 256;
                int h = idx >> 5, rr = idx & 31;
                g_ZTt[h * 4096 + n0 + rr] = sT[rr * 129 + h];
            }
        }
    } else if (blockIdx.x < 272) {
        int* s_is64 = reinterpret_cast<int*>(s_buf);
        if (tid == 0) *s_is64 = 1;
        __syncthreads();
        const int* p32 = reinterpret_cast<const int*>(edge);
        if (p32[2*tid + 1] != 0) *s_is64 = 0;
        __syncthreads();
        const int is64 = *s_is64;

        const int wid = tid >> 5, lane = tid & 31;
        const int e = (blockIdx.x - 144) * 8 + wid;
        int src, dst;
        if (is64) {
            const long long* p = reinterpret_cast<const long long*>(edge);
            src = (int)p[e]; dst = (int)p[EE + e];
        } else {
            src = p32[e]; dst = p32[EE + e];
        }
        float4 xs = *reinterpret_cast<const float4*>(hlx + src * 128 + lane * 4);
        float4 xd = *reinterpret_cast<const float4*>(hlx + dst * 128 + lane * 4);
        float acc[6];
#pragma unroll
        for (int j = 0; j < 6; j++) acc[j] = 0.f;
        const float* xsv = reinterpret_cast<const float*>(&xs);
        const float* xdv = reinterpret_cast<const float*>(&xd);
#pragma unroll
        for (int i = 0; i < 4; i++) {
            int c = lane * 4 + i;
#pragma unroll
            for (int j = 0; j < 6; j++) {
                acc[j] += xsv[i] * __ldg(Wbd + c * 6 + j);
                acc[j] += xdv[i] * __ldg(Wbd + (128 + c) * 6 + j);
            }
        }
#pragma unroll
        for (int off = 16; off > 0; off >>= 1)
#pragma unroll
            for (int j = 0; j < 6; j++)
                acc[j] += __shfl_down_sync(0xffffffffu, acc[j], off);
        if (lane == 0)
#pragma unroll
            for (int j = 0; j < 6; j++)
                out[BOND_OFF + e * 6 + j] = acc[j] + bbd[j];
    } else if (blockIdx.x < 336) {
        float* sWat = reinterpret_cast<float*>(s_buf);      // [28][129]
        float* sX   = sWat + 28 * 129;                      // [8][128]
        const int row0 = (blockIdx.x - 272) * 8;

        for (int idx = tid; idx < 128 * 28; idx += 256) {
            int c = idx / 28, k = idx - c * 28;
            sWat[k * 129 + c] = Wat[idx];
        }
        for (int idx = tid; idx < 8 * 128; idx += 256)
            sX[idx] = hlx[row0 * 128 + idx];
        __syncthreads();

        const int r = tid >> 5, k = tid & 31;
        if (k < 28) {
            float acc = bat[k];
            const float* xr = sX + r * 128;
            const float* wr = sWat + k * 129;
#pragma unroll 8
            for (int c = 0; c < 128; c++) acc += xr[c] * wr[c];
            out[ATOM_OFF + (row0 + r) * 28 + k] = acc;
        }
    } else {
        // ---------- B-frag build: [half][ks][ns][lane] -> {bh0,bh1,bl0,bl1} ----------
#pragma unroll
        for (int i = 0; i < 4; i++) {
            int e = tid + 256 * i;              // 0..1023
            int lane = e & 31;
            int ns = (e >> 5) & 3;
            int ks = (e >> 7) & 3;
            int half = (e >> 9) & 1;
            int g = lane >> 2, tg = lane & 3;
            int n = ns * 8 + g;
            int kb = half * 64 + ks * 16 + tg * 2;

            float w0 = wcol(Wpi, Wsig, Wmu, kb,     n);
            float w1 = wcol(Wpi, Wsig, Wmu, kb + 1, n);
            float w2 = wcol(Wpi, Wsig, Wmu, kb + 8, n);
            float w3 = wcol(Wpi, Wsig, Wmu, kb + 9, n);

            __nv_bfloat162 h0 = __floats2bfloat162_rn(w0, w1);
            __nv_bfloat162 h1 = __floats2bfloat162_rn(w2, w3);
            uint32_t u0 = *reinterpret_cast<uint32_t*>(&h0);
            uint32_t u1 = *reinterpret_cast<uint32_t*>(&h1);
            __nv_bfloat162 l0 = __floats2bfloat162_rn(
                w0 - __uint_as_float(u0 << 16), w1 - __uint_as_float(u0 & 0xffff0000u));
            __nv_bfloat162 l1 = __floats2bfloat162_rn(
                w2 - __uint_as_float(u1 << 16), w3 - __uint_as_float(u1 & 0xffff0000u));
            g_Bfrag[e] = make_uint4(u0, u1,
                                    *reinterpret_cast<uint32_t*>(&l0),
                                    *reinterpret_cast<uint32_t*>(&l1));
        }
    }
}

// ================= pair kernel: HMMA, reg A-fragments + prefetch + coalesced output =================
// grid 2048 = (b*64+l) x 4 t-tiles of 128. 128 threads; warp w owns rows w*32..+31.
__global__ void __launch_bounds__(128, 5)
pair_hmma_kernel(const float* __restrict__ hlpos, const float* __restrict__ htpos,
                 const float* __restrict__ bpi, const float* __restrict__ bsig,
                 const float* __restrict__ bmu, float* __restrict__ out)
{
    extern __shared__ __align__(16) char sm[];
    const int tid  = threadIdx.x;
    const int w    = tid >> 5;
    const int lane = tid & 31;
    const int g    = lane >> 2, tg = lane & 3;

    const int bid  = blockIdx.x;
    const int bid2 = bid >> 2;          // b*64 + l
    const int tile = bid & 3;
    const int b    = bid2 >> 6;
    const int n0   = b * 512 + tile * 128;

    float* sZL   = reinterpret_cast<float*>(sm + SZL_OFF);
    float* sBias = reinterpret_cast<float*>(sm + SBIAS_OFF);

    // ---- block init ----
#pragma unroll
    for (int i = 0; i < 8; i++)
        reinterpret_cast<uint4*>(sm + SBF)[tid + 128 * i] = g_Bfrag[tid + 128 * i];
    sZL[tid] = g_ZL[bid2 * 128 + tid];
    if (tid < 32) {
        float bv = 0.f;
        if (tid < 10)      bv = bpi [tid];
        else if (tid < 20) bv = bsig[tid - 10];
        else if (tid < 30) bv = bmu [tid - 20];
        sBias[tid] = bv;
    }
    __syncthreads();

    float d[2][4][4];
#pragma unroll
    for (int ms = 0; ms < 2; ms++)
#pragma unroll
        for (int ns = 0; ns < 4; ns++)
#pragma unroll
            for (int i = 0; i < 4; i++) d[ms][ns][i] = 0.f;

    const float* zbase = g_ZTt + n0 + w * 32 + g + (tg * 2) * 4096;

    // load the 16 z-values of one step (step = half*4+ks): dst[ms*8 + {0..7}]
    auto LOADZ = [&](float* dst, int step) {
        const float* zp = zbase + (step * 16) * 4096;
#pragma unroll
        for (int ms = 0; ms < 2; ms++) {
            const float* q = zp + ms * 16;
            dst[ms*8 + 0] = q[0];            dst[ms*8 + 1] = q[8];
            dst[ms*8 + 2] = q[4096];         dst[ms*8 + 3] = q[4096 + 8];
            dst[ms*8 + 4] = q[8 * 4096];     dst[ms*8 + 5] = q[8 * 4096 + 8];
            dst[ms*8 + 6] = q[9 * 4096];     dst[ms*8 + 7] = q[9 * 4096 + 8];
        }
    };

    float zbuf[2][16];
    LOADZ(zbuf[0], 0);

#pragma unroll
    for (int step = 0; step < 8; step++) {
        // prefetch next step's z FIRST (hidden under elusplit + MMA below)
        if (step < 7) LOADZ(zbuf[(step + 1) & 1], step + 1);

        const float* cur = zbuf[step & 1];
        const int hb = step * 16 + tg * 2;
        const float zl0 = sZL[hb],     zl1 = sZL[hb + 1];
        const float zl2 = sZL[hb + 8], zl3 = sZL[hb + 9];

        uint32_t ahi[2][4], alo[2][4];
#pragma unroll
        for (int ms = 0; ms < 2; ms++) {
            elusplit(cur[ms*8 + 0] + zl0, cur[ms*8 + 2] + zl1, ahi[ms][0], alo[ms][0]);
            elusplit(cur[ms*8 + 1] + zl0, cur[ms*8 + 3] + zl1, ahi[ms][1], alo[ms][1]);
            elusplit(cur[ms*8 + 4] + zl2, cur[ms*8 + 6] + zl3, ahi[ms][2], alo[ms][2]);
            elusplit(cur[ms*8 + 5] + zl2, cur[ms*8 + 7] + zl3, ahi[ms][3], alo[ms][3]);
        }
#pragma unroll
        for (int ns = 0; ns < 4; ns++) {
            uint4 bf = *reinterpret_cast<const uint4*>(
                sm + SBF + (((step * 4 + ns) * 32 + lane) << 4));
#pragma unroll
            for (int ms = 0; ms < 2; ms++) {
                mma16816(d[ms][ns], ahi[ms], bf.x, bf.y);
                mma16816(d[ms][ns], alo[ms], bf.x, bf.y);
                mma16816(d[ms][ns], ahi[ms], bf.z, bf.w);
            }
        }
    }

    // ---- phase B: overlay D region on B frags / zL ----
    __syncthreads();

    char* sd = sm + SD_OFF + w * SD_WARP;
#pragma unroll
    for (int ms = 0; ms < 2; ms++)
#pragma unroll
        for (int ns = 0; ns < 4; ns++) {
            int r0 = ms * 16 + g;
            int cb = (ns * 8 + tg * 2) * 4;
            *reinterpret_cast<float*>(sd + r0 * 132 + cb)           = d[ms][ns][0];
            *reinterpret_cast<float*>(sd + r0 * 132 + cb + 4)       = d[ms][ns][1];
            *reinterpret_cast<float*>(sd + (r0 + 8) * 132 + cb)     = d[ms][ns][2];
            *reinterpret_cast<float*>(sd + (r0 + 8) * 132 + cb + 4) = d[ms][ns][3];
        }
    __syncwarp();

    // ---- compute head outputs in registers (thread owns pair row = tid) ----
    float pi_v[10], sig_v[10], mu_v[10], dist_v, cb_v;
    {
        const int t = tile * 128 + tid;
        const char* drow = sd + lane * 132;

        float v[30];
#pragma unroll
        for (int k = 0; k < 30; k++)
            v[k] = *reinterpret_cast<const float*>(drow + k * 4) + sBias[k];

        float m = v[0];
#pragma unroll
        for (int k = 1; k < 10; k++) m = fmaxf(m, v[k]);
        float s = 0.f;
#pragma unroll
        for (int k = 0; k < 10; k++) { pi_v[k] = __expf(v[k] - m); s += pi_v[k]; }
        float inv = __fdividef(1.f, s);
#pragma unroll
        for (int k = 0; k < 10; k++) pi_v[k] *= inv;

#pragma unroll
        for (int k = 0; k < 10; k++) {
            float x = v[10 + k];
            sig_v[k] = ((x > 0.f) ? x : (__expf(x) - 1.f)) + 1.1f;
        }
#pragma unroll
        for (int k = 0; k < 10; k++) {
            float x = v[20 + k];
            mu_v[k] = ((x > 0.f) ? x : (__expf(x) - 1.f)) + 1.0f;
        }

        const float plx = hlpos[bid2 * 3 + 0];
        const float ply = hlpos[bid2 * 3 + 1];
        const float plz = hlpos[bid2 * 3 + 2];
        const float* pt = htpos + (b * 512 + t) * 3;
        float d2 = -2.f * (plx * pt[0] + ply * pt[1] + plz * pt[2])
                 + (pt[0]*pt[0] + pt[1]*pt[1] + pt[2]*pt[2])
                 + (plx*plx + ply*ply + plz*plz);
        dist_v = sqrtf(d2);
        cb_v = (float)b;
    }

    // ---- phase C: overlay output staging buffer; write GMEM coalesced ----
    __syncthreads();     // everyone done reading sd
    float* sOut = reinterpret_cast<float*>(sm);   // [3][1280] floats = 15360 B
#pragma unroll
    for (int k = 0; k < 10; k++) {
        sOut[tid * 10 + k]        = pi_v[k];
        sOut[1280 + tid * 10 + k] = sig_v[k];
        sOut[2560 + tid * 10 + k] = mu_v[k];
    }
    __syncthreads();

    {
        const int pbase = bid2 * 512 + tile * 128;   // block's first pair row
        const long obase = (long)pbase * 10;
#pragma unroll
        for (int j = 0; j < 10; j++) {
            out[PI_OFF  + obase + j * 128 + tid] = sOut[j * 128 + tid];
            out[SIG_OFF + obase + j * 128 + tid] = sOut[1280 + j * 128 + tid];
            out[MU_OFF  + obase + j * 128 + tid] = sOut[2560 + j * 128 + tid];
        }
        out[DIST_OFF + pbase + tid] = dist_v;
        out[CB_OFF   + pbase + tid] = cb_v;
    }
}

// ---------------- launch ----------------
extern "C" void kernel_launch(void* const* d_in, const int* in_sizes, int n_in,
                              void* d_out, int out_size)
{
    const float* hlx   = (const float*)d_in[0];
    const float* htx   = (const float*)d_in[1];
    const float* hlpos = (const float*)d_in[2];
    const float* htpos = (const float*)d_in[3];
    const void*  edge  = d_in[4];
    const float* W1    = (const float*)d_in[5];
    const float* b1    = (const float*)d_in[6];
    const float* gamma = (const float*)d_in[7];
    const float* beta  = (const float*)d_in[8];
    const float* rmean = (const float*)d_in[9];
    const float* rvar  = (const float*)d_in[10];
    const float* Wpi   = (const float*)d_in[11];
    const float* bpi   = (const float*)d_in[12];
    const float* Wsig  = (const float*)d_in[13];
    const float* bsig  = (const float*)d_in[14];
    const float* Wmu   = (const float*)d_in[15];
    const float* bmu   = (const float*)d_in[16];
    const float* Wat   = (const float*)d_in[17];
    const float* bat   = (const float*)d_in[18];
    const float* Wbd   = (const float*)d_in[19];
    const float* bbd   = (const float*)d_in[20];
    float* out = (float*)d_out;

    cudaFuncSetAttribute(pair_hmma_kernel, cudaFuncAttributeMaxDynamicSharedMemorySize, SMEM_TOTAL);

    prep_kernel<<<337, 256>>>(hlx, htx, edge, W1, b1, gamma, beta, rmean, rvar,
                              Wat, bat, Wbd, bbd, Wpi, Wsig, Wmu, out);
    pair_hmma_kernel<<<2048, 128, SMEM_TOTAL>>>(hlpos, htpos, bpi, bsig, bmu, out);
}